// round 11
// baseline (speedup 1.0000x reference)
#include <cuda_runtime.h>
#include <cuda_bf16.h>
#include <stdint.h>

#define NSP   4096
#define CCH   64
#define BATCH 4
#define KT    128
#define NTILES (NSP / KT)
#define NQT   (NSP / 128)      // 32 q-tiles
#define NSPLIT 2
#define TILES_PER_SPLIT (NTILES / NSPLIT)

// ---------------------------------------------------------------------------
// Scratch
// ---------------------------------------------------------------------------
__device__ float         g_q [BATCH * NSP * 8];
__device__ uint32_t      g_kp[BATCH * NSP * 8];
__device__ __nv_bfloat16 g_v [(size_t)BATCH * CCH * NSP];
__device__ float         g_po[(size_t)NSPLIT * BATCH * NQT * CCH * 128];
__device__ float         g_pl[NSPLIT * BATCH * NQT * 128];

#define LOG2E 1.4426950408889634f

__device__ __forceinline__ void mma_16x8x16(
    float c[4], uint32_t a0, uint32_t a1, uint32_t a2, uint32_t a3,
    uint32_t b0, uint32_t b1)
{
    asm volatile(
        "mma.sync.aligned.m16n8k16.row.col.f32.bf16.bf16.f32 "
        "{%0,%1,%2,%3}, {%4,%5,%6,%7}, {%8,%9}, {%0,%1,%2,%3};"
        : "+f"(c[0]), "+f"(c[1]), "+f"(c[2]), "+f"(c[3])
        : "r"(a0), "r"(a1), "r"(a2), "r"(a3), "r"(b0), "r"(b1));
}
__device__ __forceinline__ void mma_16x8x8(
    float c[4], uint32_t a0, uint32_t a1, uint32_t b0)
{
    asm volatile(
        "mma.sync.aligned.m16n8k8.row.col.f32.bf16.bf16.f32 "
        "{%0,%1,%2,%3}, {%4,%5}, {%6}, {%0,%1,%2,%3};"
        : "+f"(c[0]), "+f"(c[1]), "+f"(c[2]), "+f"(c[3])
        : "r"(a0), "r"(a1), "r"(b0));
}
__device__ __forceinline__ void ldsm_x4(
    uint32_t& r0, uint32_t& r1, uint32_t& r2, uint32_t& r3, uint32_t addr)
{
    asm volatile("ldmatrix.sync.aligned.m8n8.x4.shared.b16 {%0,%1,%2,%3}, [%4];"
        : "=r"(r0), "=r"(r1), "=r"(r2), "=r"(r3) : "r"(addr));
}
__device__ __forceinline__ uint32_t cvt_bf16x2(float hi, float lo) {
    uint32_t r;
    asm("cvt.rn.bf16x2.f32 %0, %1, %2;" : "=r"(r) : "f"(hi), "f"(lo));
    return r;
}
__device__ __forceinline__ float ex2f(float x) {
    float r;
    asm("ex2.approx.f32 %0, %1;" : "=f"(r) : "f"(x));
    return r;
}
__device__ __forceinline__ void split_bf16(float v, uint16_t& h, uint16_t& l) {
    __nv_bfloat16 hb = __float2bfloat16(v);
    __nv_bfloat16 lb = __float2bfloat16(v - __bfloat162float(hb));
    h = __bfloat16_as_ushort(hb);
    l = __bfloat16_as_ushort(lb);
}
__device__ __forceinline__ uint32_t smem_u32(const void* p) {
    uint32_t a;
    asm("{ .reg .u64 t; cvta.to.shared.u64 t, %1; cvt.u32.u64 %0, t; }"
        : "=r"(a) : "l"(p));
    return a;
}
__device__ __forceinline__ void cp_async16(uint32_t dst, const void* src) {
    asm volatile("cp.async.cg.shared.global [%0], [%1], 16;"
                 :: "r"(dst), "l"(src));
}
#define CP_COMMIT() asm volatile("cp.async.commit_group;" ::: "memory")
#define CP_WAIT0()  asm volatile("cp.async.wait_group 0;" ::: "memory")

// ---------------------------------------------------------------------------
// Projection v5 (unchanged): x tile staged via cp.async; broadcast weights.
// ---------------------------------------------------------------------------
#define XS_STR 68

__global__ __launch_bounds__(256) void proj_kernel(
    const float* __restrict__ x,
    const float* __restrict__ wq, const float* __restrict__ bq,
    const float* __restrict__ wk, const float* __restrict__ bk,
    const float* __restrict__ wv, const float* __restrict__ bv)
{
    __shared__ __align__(16) float w_t[64 * 80];       // [c][o]
    __shared__ __align__(16) float x_s[64 * XS_STR];   // [c][n] tile
    __shared__ float b_s[80];
    const int tid = threadIdx.x;
    const int b   = blockIdx.y;
    const int n0  = blockIdx.x * 64;

    {
        const float* xb = x + (size_t)b * CCH * NSP + n0;
        const uint32_t xs = smem_u32(x_s);
        #pragma unroll
        for (int i = 0; i < 4; i++) {
            int idx = tid + i * 256;
            int c   = idx >> 4;
            int seg = idx & 15;
            cp_async16(xs + (c * XS_STR + seg * 4) * 4,
                       xb + (size_t)c * NSP + seg * 4);
        }
        CP_COMMIT();
    }

    for (int i = tid; i < 8 * 64;  i += 256) { int o = i >> 6, c = i & 63; w_t[c * 80 + o]      = wq[i]; }
    for (int i = tid; i < 8 * 64;  i += 256) { int o = i >> 6, c = i & 63; w_t[c * 80 + 8 + o]  = wk[i]; }
    for (int i = tid; i < 64 * 64; i += 256) { int o = i >> 6, c = i & 63; w_t[c * 80 + 16 + o] = wv[i]; }
    if (tid < 8)       b_s[tid] = bq[tid];
    else if (tid < 16) b_s[tid] = bk[tid - 8];
    else if (tid < 80) b_s[tid] = bv[tid - 16];
    CP_WAIT0();
    __syncthreads();

    const int qu = tid >> 6;
    const int nl = tid & 63;
    const int n  = n0 + nl;
    const int obase = qu * 20;

    float acc[20];
    #pragma unroll
    for (int j = 0; j < 20; j++) acc[j] = b_s[obase + j];

    #pragma unroll 8
    for (int c = 0; c < CCH; c++) {
        float xv = x_s[c * XS_STR + nl];
        const float4* wp = (const float4*)(w_t + c * 80 + obase);
        #pragma unroll
        for (int j = 0; j < 5; j++) {
            float4 w4 = wp[j];
            acc[4*j]   += w4.x * xv;
            acc[4*j+1] += w4.y * xv;
            acc[4*j+2] += w4.z * xv;
            acc[4*j+3] += w4.w * xv;
        }
    }

    __nv_bfloat16* vp = g_v + (size_t)b * CCH * NSP + n;
    if (qu == 0) {
        float* qp = g_q + ((size_t)b * NSP + n) * 8;
        #pragma unroll
        for (int i = 0; i < 8; i++) qp[i] = acc[i] * LOG2E;

        uint16_t kh[8], kl[8];
        #pragma unroll
        for (int i = 0; i < 8; i++) split_bf16(acc[8 + i], kh[i], kl[i]);
        uint32_t row[8];
        #pragma unroll
        for (int i = 0; i < 4; i++) {
            row[i]     = (uint32_t)kh[2*i] | ((uint32_t)kh[2*i+1] << 16);
            row[4 + i] = (uint32_t)kl[2*i] | ((uint32_t)kl[2*i+1] << 16);
        }
        uint4* kp = (uint4*)(g_kp + ((size_t)b * NSP + n) * 8);
        kp[0] = ((uint4*)row)[0];
        kp[1] = ((uint4*)row)[1];

        #pragma unroll
        for (int j = 0; j < 4; j++)
            vp[(size_t)j * NSP] = __float2bfloat16(acc[16 + j]);
    } else {
        const int cbase = qu * 20 - 16;
        #pragma unroll
        for (int j = 0; j < 20; j++)
            vp[(size_t)(cbase + j) * NSP] = __float2bfloat16(acc[j]);
    }
}

// ---------------------------------------------------------------------------
// Split-KV flash attention with ldmatrix B-fragment loads.
// Grid (32, 4, 2) = 256 CTAs; warp owns 16 q-rows x full 128-key tiles.
// ---------------------------------------------------------------------------
#define K_STR 48
#define V_STR 272
#define KBUF_SZ (128 * K_STR)          // 6144
#define VBUF_SZ (64 * V_STR)           // 17408
#define VBASE   (2 * KBUF_SZ)          // 12288
#define SMEM_SZ (VBASE + 2 * VBUF_SZ)  // 47104
#define STAGE_STR 132

__global__ __launch_bounds__(256) void attn_kernel()
{
    __shared__ __align__(16) char s_buf[SMEM_SZ];

    const int tid  = threadIdx.x;
    const int wid  = tid >> 5;
    const int lane = tid & 31;
    const int g    = lane >> 2;
    const int tg   = lane & 3;
    const int b    = blockIdx.y;
    const int sp   = blockIdx.z;
    const int qt   = blockIdx.x;
    const int qbase = qt * 128;

    const uint32_t sbase = smem_u32(s_buf);

    // ldmatrix lane roles: mat = lane>>3 (0..3), row_lane = lane&7.
    // Group (x4) covers t-pair: mats {0,1} -> t0 (b0,b1), mats {2,3} -> t1.
    const int mat      = lane >> 3;
    const int row_lane = lane & 7;
    const uint32_t k_lm_off = (uint32_t)(((mat >> 1) * 8 + row_lane) * K_STR + (mat & 1) * 16);
    const uint32_t v_lm_off = (uint32_t)(((mat >> 1) * 8 + row_lane) * V_STR + (mat & 1) * 16);

    // ---- persistent Q fragments ----
    uint32_t qh_r0, qh_r1, ql_r0, ql_r1;
    {
        const int r0 = qbase + wid * 16 + g;
        float2 q0 = *(const float2*)(g_q + ((size_t)b * NSP + r0) * 8 + tg * 2);
        float2 q1 = *(const float2*)(g_q + ((size_t)b * NSP + r0 + 8) * 8 + tg * 2);
        uint16_t h0, l0, h1, l1;
        split_bf16(q0.x, h0, l0); split_bf16(q0.y, h1, l1);
        qh_r0 = (uint32_t)h0 | ((uint32_t)h1 << 16);
        ql_r0 = (uint32_t)l0 | ((uint32_t)l1 << 16);
        split_bf16(q1.x, h0, l0); split_bf16(q1.y, h1, l1);
        qh_r1 = (uint32_t)h0 | ((uint32_t)h1 << 16);
        ql_r1 = (uint32_t)l0 | ((uint32_t)l1 << 16);
    }

    float oc[8][4];
    #pragma unroll
    for (int t = 0; t < 8; t++)
        #pragma unroll
        for (int i = 0; i < 4; i++) oc[t][i] = 0.f;
    float lsum0 = 0.f, lsum1 = 0.f;

    const uint32_t* gk = g_kp + (size_t)b * NSP * 8;
    const __nv_bfloat16* gv = g_v + (size_t)b * CCH * NSP;

    const int k_key  = tid >> 1;
    const int k_part = tid & 1;
    auto load_tile = [&](int kt, int buf) {
        cp_async16(sbase + buf * KBUF_SZ + k_key * K_STR + k_part * 16,
                   gk + ((size_t)kt * KT + k_key) * 8 + k_part * 4);
        #pragma unroll
        for (int i = 0; i < 4; i++) {
            int idx = tid + i * 256;
            int c = idx >> 4, seg = idx & 15;
            cp_async16(sbase + VBASE + buf * VBUF_SZ + c * V_STR + seg * 16,
                       gv + (size_t)c * NSP + kt * KT + seg * 8);
        }
    };

    const int kt0 = sp * TILES_PER_SPLIT;
    load_tile(kt0, 0);
    CP_COMMIT();

    for (int it = 0; it < TILES_PER_SPLIT; it++) {
        const int cur = it & 1;
        CP_WAIT0();
        __syncthreads();
        if (it + 1 < TILES_PER_SPLIT) {
            load_tile(kt0 + it + 1, cur ^ 1);
            CP_COMMIT();
        }

        const uint32_t k_lm = sbase + cur * KBUF_SZ + k_lm_off;
        const uint32_t v_lm = sbase + VBASE + cur * VBUF_SZ + v_lm_off;

        // ---- MMA1: S = Q K^T; 8 ldmatrix.x4 (2 t's each) ----
        float sc[16][4];
        #pragma unroll
        for (int tp = 0; tp < 8; tp++) {
            uint32_t b00, b01, b10, b11;
            ldsm_x4(b00, b01, b10, b11, k_lm + (uint32_t)(tp * 16 * K_STR));
            const int t0 = 2 * tp, t1 = 2 * tp + 1;
            #pragma unroll
            for (int i = 0; i < 4; i++) { sc[t0][i] = 0.f; sc[t1][i] = 0.f; }
            mma_16x8x16(sc[t0], qh_r0, qh_r1, qh_r0, qh_r1, b00, b01);
            mma_16x8x8 (sc[t0], ql_r0, ql_r1, b00);
            mma_16x8x16(sc[t1], qh_r0, qh_r1, qh_r0, qh_r1, b10, b11);
            mma_16x8x8 (sc[t1], ql_r0, ql_r1, b10);
        }

        // ---- exp + pack P ----
        uint32_t pa[8][4];
        #pragma unroll
        for (int kk = 0; kk < 8; kk++) {
            float e00 = ex2f(sc[2*kk][0]),   e01 = ex2f(sc[2*kk][1]);
            float e02 = ex2f(sc[2*kk][2]),   e03 = ex2f(sc[2*kk][3]);
            float e10 = ex2f(sc[2*kk+1][0]), e11 = ex2f(sc[2*kk+1][1]);
            float e12 = ex2f(sc[2*kk+1][2]), e13 = ex2f(sc[2*kk+1][3]);
            lsum0 += (e00 + e01) + (e10 + e11);
            lsum1 += (e02 + e03) + (e12 + e13);
            pa[kk][0] = cvt_bf16x2(e01, e00);
            pa[kk][1] = cvt_bf16x2(e03, e02);
            pa[kk][2] = cvt_bf16x2(e11, e10);
            pa[kk][3] = cvt_bf16x2(e13, e12);
        }

        // ---- MMA2: O += P V^T; 32 ldmatrix.x4 ----
        #pragma unroll
        for (int kk = 0; kk < 8; kk++) {
            #pragma unroll
            for (int tp = 0; tp < 4; tp++) {
                uint32_t b00, b01, b10, b11;
                ldsm_x4(b00, b01, b10, b11,
                        v_lm + (uint32_t)(tp * 16 * V_STR + kk * 32));
                mma_16x8x16(oc[2*tp],   pa[kk][0], pa[kk][1], pa[kk][2], pa[kk][3], b00, b01);
                mma_16x8x16(oc[2*tp+1], pa[kk][0], pa[kk][1], pa[kk][2], pa[kk][3], b10, b11);
            }
        }
    }

    // ---- emit partial lsum (quad-reduced) ----
    lsum0 += __shfl_xor_sync(0xFFFFFFFF, lsum0, 1);
    lsum0 += __shfl_xor_sync(0xFFFFFFFF, lsum0, 2);
    lsum1 += __shfl_xor_sync(0xFFFFFFFF, lsum1, 1);
    lsum1 += __shfl_xor_sync(0xFFFFFFFF, lsum1, 2);
    const int pbase = ((sp * BATCH + b) * NQT + qt);
    if (tg == 0) {
        g_pl[pbase * 128 + wid * 16 + g]     = lsum0;
        g_pl[pbase * 128 + wid * 16 + g + 8] = lsum1;
    }

    // ---- stage unnormalized O, write partial coalesced ----
    __syncthreads();
    float* stage = (float*)s_buf;
    const int n0 = wid * 16 + g;
    #pragma unroll
    for (int t = 0; t < 8; t++) {
        const int c = t * 8 + tg * 2;
        stage[c * STAGE_STR + n0]           = oc[t][0];
        stage[(c + 1) * STAGE_STR + n0]     = oc[t][1];
        stage[c * STAGE_STR + n0 + 8]       = oc[t][2];
        stage[(c + 1) * STAGE_STR + n0 + 8] = oc[t][3];
    }
    __syncthreads();

    float* po = g_po + (size_t)pbase * (CCH * 128);
    for (int idx = tid; idx < CCH * 128; idx += 256) {
        const int c  = idx >> 7;
        const int nn = idx & 127;
        po[idx] = stage[c * STAGE_STR + nn];
    }
}

// ---------------------------------------------------------------------------
// Combine: out = x + gamma * (O0 + O1) / (l0 + l1).
// ---------------------------------------------------------------------------
__global__ __launch_bounds__(256) void combine_kernel(
    const float* __restrict__ x,
    const float* __restrict__ gamma,
    float* __restrict__ out)
{
    __shared__ float sinv[128];
    const int tid = threadIdx.x;
    const int qt  = blockIdx.x;
    const int b   = blockIdx.y;

    const int p0 = ((0 * BATCH + b) * NQT + qt);
    const int p1 = ((1 * BATCH + b) * NQT + qt);

    if (tid < 128) {
        float l = g_pl[p0 * 128 + tid] + g_pl[p1 * 128 + tid];
        sinv[tid] = __ldg(gamma) / l;
    }
    __syncthreads();

    const float* po0 = g_po + (size_t)p0 * (CCH * 128);
    const float* po1 = g_po + (size_t)p1 * (CCH * 128);
    const size_t base = (size_t)b * CCH * NSP + (size_t)qt * 128;

    for (int idx = tid; idx < CCH * 128; idx += 256) {
        const int c  = idx >> 7;
        const int nn = idx & 127;
        const size_t off = base + (size_t)c * NSP + nn;
        out[off] = x[off] + (po0[idx] + po1[idx]) * sinv[nn];
    }
}

extern "C" void kernel_launch(void* const* d_in, const int* in_sizes, int n_in,
                              void* d_out, int out_size)
{
    const float* x     = (const float*)d_in[0];
    const float* wq    = (const float*)d_in[1];
    const float* bq    = (const float*)d_in[2];
    const float* wk    = (const float*)d_in[3];
    const float* bk    = (const float*)d_in[4];
    const float* wv    = (const float*)d_in[5];
    const float* bv    = (const float*)d_in[6];
    const float* gamma = (const float*)d_in[7];
    float* out = (float*)d_out;

    dim3 pg(NSP / 64, BATCH);
    proj_kernel<<<pg, 256>>>(x, wq, bq, wk, bk, wv, bv);

    dim3 ag(NQT, BATCH, NSPLIT);
    attn_kernel<<<ag, 256>>>();

    dim3 cg(NQT, BATCH);
    combine_kernel<<<cg, 256>>>(x, gamma, out);
}

// round 12
// speedup vs baseline: 1.0644x; 1.0644x over previous
#include <cuda_runtime.h>
#include <cuda_bf16.h>
#include <stdint.h>

#define NSP   4096
#define CCH   64
#define BATCH 4
#define KT    128
#define NTILES (NSP / KT)
#define NQT   (NSP / 128)      // 32 q-tiles
#define NSPLIT 2
#define TILES_PER_SPLIT (NTILES / NSPLIT)

// ---------------------------------------------------------------------------
// Scratch
// ---------------------------------------------------------------------------
__device__ float         g_q [BATCH * NSP * 8];
__device__ uint32_t      g_kp[BATCH * NSP * 8];
__device__ __nv_bfloat16 g_v [(size_t)BATCH * CCH * NSP];
__device__ float         g_po[(size_t)NSPLIT * BATCH * NQT * CCH * 128];
__device__ float         g_pl[NSPLIT * BATCH * NQT * 128];

#define LOG2E 1.4426950408889634f

__device__ __forceinline__ void mma_16x8x16(
    float c[4], uint32_t a0, uint32_t a1, uint32_t a2, uint32_t a3,
    uint32_t b0, uint32_t b1)
{
    asm volatile(
        "mma.sync.aligned.m16n8k16.row.col.f32.bf16.bf16.f32 "
        "{%0,%1,%2,%3}, {%4,%5,%6,%7}, {%8,%9}, {%0,%1,%2,%3};"
        : "+f"(c[0]), "+f"(c[1]), "+f"(c[2]), "+f"(c[3])
        : "r"(a0), "r"(a1), "r"(a2), "r"(a3), "r"(b0), "r"(b1));
}
__device__ __forceinline__ void mma_16x8x8(
    float c[4], uint32_t a0, uint32_t a1, uint32_t b0)
{
    asm volatile(
        "mma.sync.aligned.m16n8k8.row.col.f32.bf16.bf16.f32 "
        "{%0,%1,%2,%3}, {%4,%5}, {%6}, {%0,%1,%2,%3};"
        : "+f"(c[0]), "+f"(c[1]), "+f"(c[2]), "+f"(c[3])
        : "r"(a0), "r"(a1), "r"(b0));
}
__device__ __forceinline__ void ldsm_x4(
    uint32_t& r0, uint32_t& r1, uint32_t& r2, uint32_t& r3, uint32_t addr)
{
    asm volatile("ldmatrix.sync.aligned.m8n8.x4.shared.b16 {%0,%1,%2,%3}, [%4];"
        : "=r"(r0), "=r"(r1), "=r"(r2), "=r"(r3) : "r"(addr));
}
__device__ __forceinline__ uint32_t cvt_bf16x2(float hi, float lo) {
    uint32_t r;
    asm("cvt.rn.bf16x2.f32 %0, %1, %2;" : "=r"(r) : "f"(hi), "f"(lo));
    return r;
}
__device__ __forceinline__ float ex2f(float x) {
    float r;
    asm("ex2.approx.f32 %0, %1;" : "=f"(r) : "f"(x));
    return r;
}
__device__ __forceinline__ void split_bf16(float v, uint16_t& h, uint16_t& l) {
    __nv_bfloat16 hb = __float2bfloat16(v);
    __nv_bfloat16 lb = __float2bfloat16(v - __bfloat162float(hb));
    h = __bfloat16_as_ushort(hb);
    l = __bfloat16_as_ushort(lb);
}
__device__ __forceinline__ uint32_t smem_u32(const void* p) {
    uint32_t a;
    asm("{ .reg .u64 t; cvta.to.shared.u64 t, %1; cvt.u32.u64 %0, t; }"
        : "=r"(a) : "l"(p));
    return a;
}
__device__ __forceinline__ void cp_async16(uint32_t dst, const void* src) {
    asm volatile("cp.async.cg.shared.global [%0], [%1], 16;"
                 :: "r"(dst), "l"(src));
}
#define CP_COMMIT() asm volatile("cp.async.commit_group;" ::: "memory")
#define CP_WAIT0()  asm volatile("cp.async.wait_group 0;" ::: "memory")

// ---------------------------------------------------------------------------
// Projection v6 — tensor-core GEMM: Out[80, n64] = W[80,64] @ x[64, n64] + b.
// 3-term split-bf16 (Wh*Xh + Wh*Xl + Wl*Xh) for fp32-grade accuracy.
// Fragment recipes identical to the (validated) attn kernel:
//   A frag: a0=[row g, k 2tg], a1=[row g+8], a2=[row g, k+8], a3=[row g+8, k+8]
//   B frag: b0=[n row g, k 2tg], b1=[n row g, k+8]  (from x^T [n][c] smem)
//   C frag: c0,c1=[row g, col 2tg/+1], c2,c3=[row g+8, ...]
// Grid (64, 4) x 128 thr (4 warps; warp owns 16 n-columns).
// ---------------------------------------------------------------------------
#define WS_STR 66   // bf16; (66*o + c)/2 = 33o + c/2, 33 odd -> conflict-free
#define XT_STR 70   // bf16; word = 35n + c/2, 35 odd -> conflict-free
#define QK_STR 68   // fp32 stage stride

__global__ __launch_bounds__(128) void proj_kernel(
    const float* __restrict__ x,
    const float* __restrict__ wq, const float* __restrict__ bq,
    const float* __restrict__ wk, const float* __restrict__ bk,
    const float* __restrict__ wv, const float* __restrict__ bv)
{
    __shared__ __align__(16) uint16_t wh_s[80 * WS_STR];
    __shared__ __align__(16) uint16_t wl_s[80 * WS_STR];
    __shared__ __align__(16) uint16_t xh_s[64 * XT_STR];   // x^T [n][c]
    __shared__ __align__(16) uint16_t xl_s[64 * XT_STR];
    __shared__ __align__(16) float    qk_s[16 * QK_STR];
    __shared__ float b_s[80];

    const int tid  = threadIdx.x;
    const int lane = tid & 31;
    const int wrp  = tid >> 5;           // 0..3
    const int g    = lane >> 2;
    const int tg   = lane & 3;
    const int b    = blockIdx.y;
    const int n0   = blockIdx.x * 64;

    // ---- W -> split bf16 smem [o][c] (2560 c-pairs, 20 per thread) ----
    #pragma unroll
    for (int i = 0; i < 20; i++) {
        int idx = tid + i * 128;
        int o = idx >> 5, c = (idx & 31) * 2;
        float2 w2;
        if (o < 8)       w2 = *(const float2*)(wq + o * 64 + c);
        else if (o < 16) w2 = *(const float2*)(wk + (o - 8) * 64 + c);
        else             w2 = *(const float2*)(wv + (o - 16) * 64 + c);
        uint16_t h0, l0, h1, l1;
        split_bf16(w2.x, h0, l0); split_bf16(w2.y, h1, l1);
        *(uint32_t*)(wh_s + o * WS_STR + c) = (uint32_t)h0 | ((uint32_t)h1 << 16);
        *(uint32_t*)(wl_s + o * WS_STR + c) = (uint32_t)l0 | ((uint32_t)l1 << 16);
    }
    if (tid < 8)       b_s[tid] = bq[tid];
    else if (tid < 16) b_s[tid] = bk[tid - 8];
    else if (tid < 80) b_s[tid] = bv[tid - 16];

    // ---- x tile -> split bf16 TRANSPOSED smem [n][c] ----
    {
        const float* xb = x + (size_t)b * CCH * NSP + n0;
        #pragma unroll
        for (int i = 0; i < 8; i++) {
            int idx = tid + i * 128;            // 1024 float4 chunks
            int c = idx >> 4, nq = idx & 15;
            float4 v = *(const float4*)(xb + (size_t)c * NSP + 4 * nq);
            uint16_t h, l;
            split_bf16(v.x, h, l); xh_s[(4*nq+0) * XT_STR + c] = h; xl_s[(4*nq+0) * XT_STR + c] = l;
            split_bf16(v.y, h, l); xh_s[(4*nq+1) * XT_STR + c] = h; xl_s[(4*nq+1) * XT_STR + c] = l;
            split_bf16(v.z, h, l); xh_s[(4*nq+2) * XT_STR + c] = h; xl_s[(4*nq+2) * XT_STR + c] = l;
            split_bf16(v.w, h, l); xh_s[(4*nq+3) * XT_STR + c] = h; xl_s[(4*nq+3) * XT_STR + c] = l;
        }
    }
    __syncthreads();

    // ---- MMA mainloop: C[5 mt][2 nt][4] ----
    float C[5][2][4];
    #pragma unroll
    for (int mt = 0; mt < 5; mt++)
        #pragma unroll
        for (int nt = 0; nt < 2; nt++)
            #pragma unroll
            for (int i = 0; i < 4; i++) C[mt][nt][i] = 0.f;

    #pragma unroll
    for (int ks = 0; ks < 4; ks++) {
        uint32_t Ah[5][4], Al[5][4];
        #pragma unroll
        for (int mt = 0; mt < 5; mt++) {
            const int r0 = (16 * mt + g) * WS_STR + 16 * ks + 2 * tg;
            const int r1 = r0 + 8 * WS_STR;
            Ah[mt][0] = *(const uint32_t*)(wh_s + r0);
            Ah[mt][1] = *(const uint32_t*)(wh_s + r1);
            Ah[mt][2] = *(const uint32_t*)(wh_s + r0 + 8);
            Ah[mt][3] = *(const uint32_t*)(wh_s + r1 + 8);
            Al[mt][0] = *(const uint32_t*)(wl_s + r0);
            Al[mt][1] = *(const uint32_t*)(wl_s + r1);
            Al[mt][2] = *(const uint32_t*)(wl_s + r0 + 8);
            Al[mt][3] = *(const uint32_t*)(wl_s + r1 + 8);
        }
        #pragma unroll
        for (int nt = 0; nt < 2; nt++) {
            const int nr = (wrp * 16 + nt * 8 + g) * XT_STR + 16 * ks + 2 * tg;
            uint32_t Bh0 = *(const uint32_t*)(xh_s + nr);
            uint32_t Bh1 = *(const uint32_t*)(xh_s + nr + 8);
            uint32_t Bl0 = *(const uint32_t*)(xl_s + nr);
            uint32_t Bl1 = *(const uint32_t*)(xl_s + nr + 8);
            #pragma unroll
            for (int mt = 0; mt < 5; mt++) {
                mma_16x8x16(C[mt][nt], Ah[mt][0], Ah[mt][1], Ah[mt][2], Ah[mt][3], Bh0, Bh1);
                mma_16x8x16(C[mt][nt], Ah[mt][0], Ah[mt][1], Ah[mt][2], Ah[mt][3], Bl0, Bl1);
                mma_16x8x16(C[mt][nt], Al[mt][0], Al[mt][1], Al[mt][2], Al[mt][3], Bh0, Bh1);
            }
        }
    }

    // ---- bias ----
    #pragma unroll
    for (int mt = 0; mt < 5; mt++) {
        const float blo = b_s[16 * mt + g];
        const float bhi = b_s[16 * mt + g + 8];
        #pragma unroll
        for (int nt = 0; nt < 2; nt++) {
            C[mt][nt][0] += blo; C[mt][nt][1] += blo;
            C[mt][nt][2] += bhi; C[mt][nt][3] += bhi;
        }
    }

    // ---- V epilogue (mt 1..4 -> channels 0..63), direct bf16x2 stores ----
    __nv_bfloat16* vb = g_v + (size_t)b * CCH * NSP;
    #pragma unroll
    for (int mt = 1; mt < 5; mt++) {
        const int ch = 16 * mt + g - 16;
        #pragma unroll
        for (int nt = 0; nt < 2; nt++) {
            const int n = n0 + wrp * 16 + nt * 8 + 2 * tg;
            *(uint32_t*)(vb + (size_t)ch * NSP + n)       = cvt_bf16x2(C[mt][nt][1], C[mt][nt][0]);
            *(uint32_t*)(vb + (size_t)(ch + 8) * NSP + n) = cvt_bf16x2(C[mt][nt][3], C[mt][nt][2]);
        }
    }

    // ---- Q/K epilogue: stage mt0 (rows 0..15) then per-n pack ----
    #pragma unroll
    for (int nt = 0; nt < 2; nt++) {
        const int nl = wrp * 16 + nt * 8 + 2 * tg;
        *(float2*)(qk_s + g * QK_STR + nl)       = make_float2(C[0][nt][0], C[0][nt][1]);
        *(float2*)(qk_s + (g + 8) * QK_STR + nl) = make_float2(C[0][nt][2], C[0][nt][3]);
    }
    __syncthreads();

    if (tid < 64) {
        // Q: rows 0..7, pre-scaled by log2e
        const int nl = tid;
        float* qp = g_q + ((size_t)b * NSP + n0 + nl) * 8;
        float4 q0, q1;
        q0.x = qk_s[0 * QK_STR + nl] * LOG2E;
        q0.y = qk_s[1 * QK_STR + nl] * LOG2E;
        q0.z = qk_s[2 * QK_STR + nl] * LOG2E;
        q0.w = qk_s[3 * QK_STR + nl] * LOG2E;
        q1.x = qk_s[4 * QK_STR + nl] * LOG2E;
        q1.y = qk_s[5 * QK_STR + nl] * LOG2E;
        q1.z = qk_s[6 * QK_STR + nl] * LOG2E;
        q1.w = qk_s[7 * QK_STR + nl] * LOG2E;
        ((float4*)qp)[0] = q0;
        ((float4*)qp)[1] = q1;
    } else {
        // K: rows 8..15 -> split packed [kh8 | kl8]
        const int nl = tid - 64;
        uint16_t kh[8], kl[8];
        #pragma unroll
        for (int i = 0; i < 8; i++)
            split_bf16(qk_s[(8 + i) * QK_STR + nl], kh[i], kl[i]);
        uint32_t row[8];
        #pragma unroll
        for (int i = 0; i < 4; i++) {
            row[i]     = (uint32_t)kh[2*i] | ((uint32_t)kh[2*i+1] << 16);
            row[4 + i] = (uint32_t)kl[2*i] | ((uint32_t)kl[2*i+1] << 16);
        }
        uint4* kp = (uint4*)(g_kp + ((size_t)b * NSP + n0 + nl) * 8);
        kp[0] = ((uint4*)row)[0];
        kp[1] = ((uint4*)row)[1];
    }
}

// ---------------------------------------------------------------------------
// Split-KV flash attention (unchanged from R11).
// ---------------------------------------------------------------------------
#define K_STR 48
#define V_STR 272
#define KBUF_SZ (128 * K_STR)
#define VBUF_SZ (64 * V_STR)
#define VBASE   (2 * KBUF_SZ)
#define SMEM_SZ (VBASE + 2 * VBUF_SZ)
#define STAGE_STR 132

__global__ __launch_bounds__(256) void attn_kernel()
{
    __shared__ __align__(16) char s_buf[SMEM_SZ];

    const int tid  = threadIdx.x;
    const int wid  = tid >> 5;
    const int lane = tid & 31;
    const int g    = lane >> 2;
    const int tg   = lane & 3;
    const int b    = blockIdx.y;
    const int sp   = blockIdx.z;
    const int qt   = blockIdx.x;
    const int qbase = qt * 128;

    const uint32_t sbase = smem_u32(s_buf);

    const int mat      = lane >> 3;
    const int row_lane = lane & 7;
    const uint32_t k_lm_off = (uint32_t)(((mat >> 1) * 8 + row_lane) * K_STR + (mat & 1) * 16);
    const uint32_t v_lm_off = (uint32_t)(((mat >> 1) * 8 + row_lane) * V_STR + (mat & 1) * 16);

    uint32_t qh_r0, qh_r1, ql_r0, ql_r1;
    {
        const int r0 = qbase + wid * 16 + g;
        float2 q0 = *(const float2*)(g_q + ((size_t)b * NSP + r0) * 8 + tg * 2);
        float2 q1 = *(const float2*)(g_q + ((size_t)b * NSP + r0 + 8) * 8 + tg * 2);
        uint16_t h0, l0, h1, l1;
        split_bf16(q0.x, h0, l0); split_bf16(q0.y, h1, l1);
        qh_r0 = (uint32_t)h0 | ((uint32_t)h1 << 16);
        ql_r0 = (uint32_t)l0 | ((uint32_t)l1 << 16);
        split_bf16(q1.x, h0, l0); split_bf16(q1.y, h1, l1);
        qh_r1 = (uint32_t)h0 | ((uint32_t)h1 << 16);
        ql_r1 = (uint32_t)l0 | ((uint32_t)l1 << 16);
    }

    float oc[8][4];
    #pragma unroll
    for (int t = 0; t < 8; t++)
        #pragma unroll
        for (int i = 0; i < 4; i++) oc[t][i] = 0.f;
    float lsum0 = 0.f, lsum1 = 0.f;

    const uint32_t* gk = g_kp + (size_t)b * NSP * 8;
    const __nv_bfloat16* gv = g_v + (size_t)b * CCH * NSP;

    const int k_key  = tid >> 1;
    const int k_part = tid & 1;
    auto load_tile = [&](int kt, int buf) {
        cp_async16(sbase + buf * KBUF_SZ + k_key * K_STR + k_part * 16,
                   gk + ((size_t)kt * KT + k_key) * 8 + k_part * 4);
        #pragma unroll
        for (int i = 0; i < 4; i++) {
            int idx = tid + i * 256;
            int c = idx >> 4, seg = idx & 15;
            cp_async16(sbase + VBASE + buf * VBUF_SZ + c * V_STR + seg * 16,
                       gv + (size_t)c * NSP + kt * KT + seg * 8);
        }
    };

    const int kt0 = sp * TILES_PER_SPLIT;
    load_tile(kt0, 0);
    CP_COMMIT();

    for (int it = 0; it < TILES_PER_SPLIT; it++) {
        const int cur = it & 1;
        CP_WAIT0();
        __syncthreads();
        if (it + 1 < TILES_PER_SPLIT) {
            load_tile(kt0 + it + 1, cur ^ 1);
            CP_COMMIT();
        }

        const uint32_t k_lm = sbase + cur * KBUF_SZ + k_lm_off;
        const uint32_t v_lm = sbase + VBASE + cur * VBUF_SZ + v_lm_off;

        float sc[16][4];
        #pragma unroll
        for (int tp = 0; tp < 8; tp++) {
            uint32_t b00, b01, b10, b11;
            ldsm_x4(b00, b01, b10, b11, k_lm + (uint32_t)(tp * 16 * K_STR));
            const int t0 = 2 * tp, t1 = 2 * tp + 1;
            #pragma unroll
            for (int i = 0; i < 4; i++) { sc[t0][i] = 0.f; sc[t1][i] = 0.f; }
            mma_16x8x16(sc[t0], qh_r0, qh_r1, qh_r0, qh_r1, b00, b01);
            mma_16x8x8 (sc[t0], ql_r0, ql_r1, b00);
            mma_16x8x16(sc[t1], qh_r0, qh_r1, qh_r0, qh_r1, b10, b11);
            mma_16x8x8 (sc[t1], ql_r0, ql_r1, b10);
        }

        uint32_t pa[8][4];
        #pragma unroll
        for (int kk = 0; kk < 8; kk++) {
            float e00 = ex2f(sc[2*kk][0]),   e01 = ex2f(sc[2*kk][1]);
            float e02 = ex2f(sc[2*kk][2]),   e03 = ex2f(sc[2*kk][3]);
            float e10 = ex2f(sc[2*kk+1][0]), e11 = ex2f(sc[2*kk+1][1]);
            float e12 = ex2f(sc[2*kk+1][2]), e13 = ex2f(sc[2*kk+1][3]);
            lsum0 += (e00 + e01) + (e10 + e11);
            lsum1 += (e02 + e03) + (e12 + e13);
            pa[kk][0] = cvt_bf16x2(e01, e00);
            pa[kk][1] = cvt_bf16x2(e03, e02);
            pa[kk][2] = cvt_bf16x2(e11, e10);
            pa[kk][3] = cvt_bf16x2(e13, e12);
        }

        #pragma unroll
        for (int kk = 0; kk < 8; kk++) {
            #pragma unroll
            for (int tp = 0; tp < 4; tp++) {
                uint32_t b00, b01, b10, b11;
                ldsm_x4(b00, b01, b10, b11,
                        v_lm + (uint32_t)(tp * 16 * V_STR + kk * 32));
                mma_16x8x16(oc[2*tp],   pa[kk][0], pa[kk][1], pa[kk][2], pa[kk][3], b00, b01);
                mma_16x8x16(oc[2*tp+1], pa[kk][0], pa[kk][1], pa[kk][2], pa[kk][3], b10, b11);
            }
        }
    }

    lsum0 += __shfl_xor_sync(0xFFFFFFFF, lsum0, 1);
    lsum0 += __shfl_xor_sync(0xFFFFFFFF, lsum0, 2);
    lsum1 += __shfl_xor_sync(0xFFFFFFFF, lsum1, 1);
    lsum1 += __shfl_xor_sync(0xFFFFFFFF, lsum1, 2);
    const int pbase = ((sp * BATCH + b) * NQT + qt);
    if (tg == 0) {
        g_pl[pbase * 128 + wid * 16 + g]     = lsum0;
        g_pl[pbase * 128 + wid * 16 + g + 8] = lsum1;
    }

    __syncthreads();
    float* stage = (float*)s_buf;
    const int n0 = wid * 16 + g;
    #pragma unroll
    for (int t = 0; t < 8; t++) {
        const int c = t * 8 + tg * 2;
        stage[c * STAGE_STR + n0]           = oc[t][0];
        stage[(c + 1) * STAGE_STR + n0]     = oc[t][1];
        stage[c * STAGE_STR + n0 + 8]       = oc[t][2];
        stage[(c + 1) * STAGE_STR + n0 + 8] = oc[t][3];
    }
    __syncthreads();

    float* po = g_po + (size_t)pbase * (CCH * 128);
    for (int idx = tid; idx < CCH * 128; idx += 256) {
        const int c  = idx >> 7;
        const int nn = idx & 127;
        po[idx] = stage[c * STAGE_STR + nn];
    }
}

// ---------------------------------------------------------------------------
// Combine (unchanged): out = x + gamma * (O0 + O1) / (l0 + l1).
// ---------------------------------------------------------------------------
__global__ __launch_bounds__(256) void combine_kernel(
    const float* __restrict__ x,
    const float* __restrict__ gamma,
    float* __restrict__ out)
{
    __shared__ float sinv[128];
    const int tid = threadIdx.x;
    const int qt  = blockIdx.x;
    const int b   = blockIdx.y;

    const int p0 = ((0 * BATCH + b) * NQT + qt);
    const int p1 = ((1 * BATCH + b) * NQT + qt);

    if (tid < 128) {
        float l = g_pl[p0 * 128 + tid] + g_pl[p1 * 128 + tid];
        sinv[tid] = __ldg(gamma) / l;
    }
    __syncthreads();

    const float* po0 = g_po + (size_t)p0 * (CCH * 128);
    const float* po1 = g_po + (size_t)p1 * (CCH * 128);
    const size_t base = (size_t)b * CCH * NSP + (size_t)qt * 128;

    for (int idx = tid; idx < CCH * 128; idx += 256) {
        const int c  = idx >> 7;
        const int nn = idx & 127;
        const size_t off = base + (size_t)c * NSP + nn;
        out[off] = x[off] + (po0[idx] + po1[idx]) * sinv[nn];
    }
}

extern "C" void kernel_launch(void* const* d_in, const int* in_sizes, int n_in,
                              void* d_out, int out_size)
{
    const float* x     = (const float*)d_in[0];
    const float* wq    = (const float*)d_in[1];
    const float* bq    = (const float*)d_in[2];
    const float* wk    = (const float*)d_in[3];
    const float* bk    = (const float*)d_in[4];
    const float* wv    = (const float*)d_in[5];
    const float* bv    = (const float*)d_in[6];
    const float* gamma = (const float*)d_in[7];
    float* out = (float*)d_out;

    dim3 pg(NSP / 64, BATCH);
    proj_kernel<<<pg, 128>>>(x, wq, bq, wk, bk, wv, bv);

    dim3 ag(NQT, BATCH, NSPLIT);
    attn_kernel<<<ag, 256>>>();

    dim3 cg(NQT, BATCH);
    combine_kernel<<<cg, 256>>>(x, gamma, out);
}

// round 14
// speedup vs baseline: 1.1055x; 1.0386x over previous
#include <cuda_runtime.h>
#include <cuda_bf16.h>
#include <stdint.h>

#define NSP   4096
#define CCH   64
#define BATCH 4
#define KT    128
#define NTILES (NSP / KT)
#define NQT   (NSP / 128)      // 32 q-tiles
#define NSPLIT 2
#define TILES_PER_SPLIT (NTILES / NSPLIT)

// ---------------------------------------------------------------------------
// Scratch
// ---------------------------------------------------------------------------
__device__ float         g_q [BATCH * NSP * 8];
__device__ uint32_t      g_kp[BATCH * NSP * 8];
__device__ __nv_bfloat16 g_v [(size_t)BATCH * CCH * NSP];
__device__ float         g_po[(size_t)NSPLIT * BATCH * NQT * CCH * 128];
__device__ float         g_pl[NSPLIT * BATCH * NQT * 128];
__device__ int           g_sem[BATCH * NQT];   // zero-init; self-resetting

#define LOG2E 1.4426950408889634f

__device__ __forceinline__ void mma_16x8x16(
    float c[4], uint32_t a0, uint32_t a1, uint32_t a2, uint32_t a3,
    uint32_t b0, uint32_t b1)
{
    asm volatile(
        "mma.sync.aligned.m16n8k16.row.col.f32.bf16.bf16.f32 "
        "{%0,%1,%2,%3}, {%4,%5,%6,%7}, {%8,%9}, {%0,%1,%2,%3};"
        : "+f"(c[0]), "+f"(c[1]), "+f"(c[2]), "+f"(c[3])
        : "r"(a0), "r"(a1), "r"(a2), "r"(a3), "r"(b0), "r"(b1));
}
__device__ __forceinline__ void mma_16x8x8(
    float c[4], uint32_t a0, uint32_t a1, uint32_t b0)
{
    asm volatile(
        "mma.sync.aligned.m16n8k8.row.col.f32.bf16.bf16.f32 "
        "{%0,%1,%2,%3}, {%4,%5}, {%6}, {%0,%1,%2,%3};"
        : "+f"(c[0]), "+f"(c[1]), "+f"(c[2]), "+f"(c[3])
        : "r"(a0), "r"(a1), "r"(b0));
}
__device__ __forceinline__ void ldsm_x4(
    uint32_t& r0, uint32_t& r1, uint32_t& r2, uint32_t& r3, uint32_t addr)
{
    asm volatile("ldmatrix.sync.aligned.m8n8.x4.shared.b16 {%0,%1,%2,%3}, [%4];"
        : "=r"(r0), "=r"(r1), "=r"(r2), "=r"(r3) : "r"(addr));
}
__device__ __forceinline__ void ldsm_x4_t(
    uint32_t& r0, uint32_t& r1, uint32_t& r2, uint32_t& r3, uint32_t addr)
{
    asm volatile("ldmatrix.sync.aligned.m8n8.x4.trans.shared.b16 {%0,%1,%2,%3}, [%4];"
        : "=r"(r0), "=r"(r1), "=r"(r2), "=r"(r3) : "r"(addr));
}
__device__ __forceinline__ uint32_t cvt_bf16x2(float hi, float lo) {
    uint32_t r;
    asm("cvt.rn.bf16x2.f32 %0, %1, %2;" : "=r"(r) : "f"(hi), "f"(lo));
    return r;
}
__device__ __forceinline__ float ex2f(float x) {
    float r;
    asm("ex2.approx.f32 %0, %1;" : "=f"(r) : "f"(x));
    return r;
}
__device__ __forceinline__ void split_bf16(float v, uint16_t& h, uint16_t& l) {
    __nv_bfloat16 hb = __float2bfloat16(v);
    __nv_bfloat16 lb = __float2bfloat16(v - __bfloat162float(hb));
    h = __bfloat16_as_ushort(hb);
    l = __bfloat16_as_ushort(lb);
}
__device__ __forceinline__ uint32_t smem_u32(const void* p) {
    uint32_t a;
    asm("{ .reg .u64 t; cvta.to.shared.u64 t, %1; cvt.u32.u64 %0, t; }"
        : "=r"(a) : "l"(p));
    return a;
}
__device__ __forceinline__ void cp_async16(uint32_t dst, const void* src) {
    asm volatile("cp.async.cg.shared.global [%0], [%1], 16;"
                 :: "r"(dst), "l"(src));
}
#define CP_COMMIT() asm volatile("cp.async.commit_group;" ::: "memory")
#define CP_WAIT0()  asm volatile("cp.async.wait_group 0;" ::: "memory")

// ---------------------------------------------------------------------------
// Projection v7b — tensor-core GEMM, ldmatrix-aligned strides.
// Out[80, n64] = W[80,64] @ x[64, n64] + b ; 3-term split bf16.
// x stays [c][n] in smem; B frags via ldmatrix.x4.trans.
// W [o][c] in smem (144B rows, 16B-aligned for ldmatrix); A via ldmatrix.x4.
// Grid (64, 4) x 256 thr; warp w owns 8 n-columns.
// ---------------------------------------------------------------------------
#define WS_STR 72   // bf16; 144B rows: 16B-aligned + ldmatrix conflict-free
#define XT_STR 72   // bf16; 144B rows
#define QK_STR 68   // fp32 stage stride

__global__ __launch_bounds__(256) void proj_kernel(
    const float* __restrict__ x,
    const float* __restrict__ wq, const float* __restrict__ bq,
    const float* __restrict__ wk, const float* __restrict__ bk,
    const float* __restrict__ wv, const float* __restrict__ bv)
{
    __shared__ __align__(16) uint16_t wh_s[80 * WS_STR];
    __shared__ __align__(16) uint16_t wl_s[80 * WS_STR];
    __shared__ __align__(16) uint16_t xh_s[64 * XT_STR];   // [c][n]
    __shared__ __align__(16) uint16_t xl_s[64 * XT_STR];
    __shared__ __align__(16) float    qk_s[16 * QK_STR];
    __shared__ float b_s[80];

    const int tid  = threadIdx.x;
    const int lane = tid & 31;
    const int wrp  = tid >> 5;           // 0..7
    const int g    = lane >> 2;
    const int tg   = lane & 3;
    const int b    = blockIdx.y;
    const int n0   = blockIdx.x * 64;

    // ---- W -> split bf16 smem [o][c] ----
    #pragma unroll
    for (int i = 0; i < 10; i++) {
        int idx = tid + i * 256;
        int o = idx >> 5, c = (idx & 31) * 2;
        float2 w2;
        if (o < 8)       w2 = *(const float2*)(wq + o * 64 + c);
        else if (o < 16) w2 = *(const float2*)(wk + (o - 8) * 64 + c);
        else             w2 = *(const float2*)(wv + (o - 16) * 64 + c);
        uint16_t h0, l0, h1, l1;
        split_bf16(w2.x, h0, l0); split_bf16(w2.y, h1, l1);
        *(uint32_t*)(wh_s + o * WS_STR + c) = (uint32_t)h0 | ((uint32_t)h1 << 16);
        *(uint32_t*)(wl_s + o * WS_STR + c) = (uint32_t)l0 | ((uint32_t)l1 << 16);
    }
    if (tid < 8)       b_s[tid] = bq[tid];
    else if (tid < 16) b_s[tid] = bk[tid - 8];
    else if (tid < 80) b_s[tid] = bv[tid - 16];

    // ---- x tile -> split bf16 smem, natural [c][n] (vectorized stores) ----
    {
        const float* xb = x + (size_t)b * CCH * NSP + n0;
        #pragma unroll
        for (int i = 0; i < 4; i++) {
            int idx = tid + i * 256;            // 1024 float4 chunks
            int c = idx >> 4, nq = (idx & 15) * 4;
            float4 v = *(const float4*)(xb + (size_t)c * NSP + nq);
            uint16_t h0, l0, h1, l1, h2, l2, h3, l3;
            split_bf16(v.x, h0, l0); split_bf16(v.y, h1, l1);
            split_bf16(v.z, h2, l2); split_bf16(v.w, h3, l3);
            *(uint32_t*)(xh_s + c * XT_STR + nq)     = (uint32_t)h0 | ((uint32_t)h1 << 16);
            *(uint32_t*)(xh_s + c * XT_STR + nq + 2) = (uint32_t)h2 | ((uint32_t)h3 << 16);
            *(uint32_t*)(xl_s + c * XT_STR + nq)     = (uint32_t)l0 | ((uint32_t)l1 << 16);
            *(uint32_t*)(xl_s + c * XT_STR + nq + 2) = (uint32_t)l2 | ((uint32_t)l3 << 16);
        }
    }
    __syncthreads();

    // ---- ldmatrix lane addressing ----
    const int lm_m  = lane >> 3;        // matrix 0..3
    const int lm_rl = lane & 7;         // row within matrix
    const uint32_t wh_base = smem_u32(wh_s);
    const uint32_t wl_base = smem_u32(wl_s);
    const uint32_t xh_base = smem_u32(xh_s);
    const uint32_t xl_base = smem_u32(xl_s);
    // A non-trans: m0 rows0-7/k0-7, m1 rows8-15/k0-7, m2 rows0-7/k8-15, m3 rows8-15/k8-15
    const uint32_t a_off = (uint32_t)((((lm_m & 1) * 8 + lm_rl) * WS_STR + (lm_m >> 1) * 8) * 2);
    // B trans (x4 covers two k16 steps): m0 k0-7, m1 k8-15, m2 k16-23, m3 k24-31
    const uint32_t b_off = (uint32_t)((((lm_m & 1) * 8 + lm_rl + (lm_m >> 1) * 16) * XT_STR + wrp * 8) * 2);

    float C[5][4];
    #pragma unroll
    for (int mt = 0; mt < 5; mt++)
        #pragma unroll
        for (int i = 0; i < 4; i++) C[mt][i] = 0.f;

    #pragma unroll
    for (int kp = 0; kp < 2; kp++) {
        uint32_t bh[2][2], bl[2][2];   // [ks within pair][b0/b1]
        ldsm_x4_t(bh[0][0], bh[0][1], bh[1][0], bh[1][1],
                  xh_base + b_off + (uint32_t)(32 * kp * XT_STR * 2));
        ldsm_x4_t(bl[0][0], bl[0][1], bl[1][0], bl[1][1],
                  xl_base + b_off + (uint32_t)(32 * kp * XT_STR * 2));
        #pragma unroll
        for (int kk = 0; kk < 2; kk++) {
            const int ks = 2 * kp + kk;
            #pragma unroll
            for (int mt = 0; mt < 5; mt++) {
                const uint32_t astep = (uint32_t)((16 * mt * WS_STR + 16 * ks) * 2);
                uint32_t ah0, ah1, ah2, ah3, al0, al1, al2, al3;
                ldsm_x4(ah0, ah1, ah2, ah3, wh_base + a_off + astep);
                ldsm_x4(al0, al1, al2, al3, wl_base + a_off + astep);
                mma_16x8x16(C[mt], ah0, ah1, ah2, ah3, bh[kk][0], bh[kk][1]);
                mma_16x8x16(C[mt], ah0, ah1, ah2, ah3, bl[kk][0], bl[kk][1]);
                mma_16x8x16(C[mt], al0, al1, al2, al3, bh[kk][0], bh[kk][1]);
            }
        }
    }

    // ---- bias ----
    #pragma unroll
    for (int mt = 0; mt < 5; mt++) {
        const float blo = b_s[16 * mt + g];
        const float bhi = b_s[16 * mt + g + 8];
        C[mt][0] += blo; C[mt][1] += blo;
        C[mt][2] += bhi; C[mt][3] += bhi;
    }

    // ---- V epilogue (mt 1..4 -> channels 0..63) ----
    __nv_bfloat16* vb = g_v + (size_t)b * CCH * NSP;
    const int nv = n0 + wrp * 8 + 2 * tg;
    #pragma unroll
    for (int mt = 1; mt < 5; mt++) {
        const int ch = 16 * mt + g - 16;
        *(uint32_t*)(vb + (size_t)ch * NSP + nv)       = cvt_bf16x2(C[mt][1], C[mt][0]);
        *(uint32_t*)(vb + (size_t)(ch + 8) * NSP + nv) = cvt_bf16x2(C[mt][3], C[mt][2]);
    }

    // ---- Q/K epilogue: stage mt0 rows 0..15 then per-n pack ----
    {
        const int nl = wrp * 8 + 2 * tg;
        *(float2*)(qk_s + g * QK_STR + nl)       = make_float2(C[0][0], C[0][1]);
        *(float2*)(qk_s + (g + 8) * QK_STR + nl) = make_float2(C[0][2], C[0][3]);
    }
    __syncthreads();

    if (tid < 64) {
        const int nl = tid;
        float* qp = g_q + ((size_t)b * NSP + n0 + nl) * 8;
        float4 q0, q1;
        q0.x = qk_s[0 * QK_STR + nl] * LOG2E;
        q0.y = qk_s[1 * QK_STR + nl] * LOG2E;
        q0.z = qk_s[2 * QK_STR + nl] * LOG2E;
        q0.w = qk_s[3 * QK_STR + nl] * LOG2E;
        q1.x = qk_s[4 * QK_STR + nl] * LOG2E;
        q1.y = qk_s[5 * QK_STR + nl] * LOG2E;
        q1.z = qk_s[6 * QK_STR + nl] * LOG2E;
        q1.w = qk_s[7 * QK_STR + nl] * LOG2E;
        ((float4*)qp)[0] = q0;
        ((float4*)qp)[1] = q1;
    } else if (tid < 128) {
        const int nl = tid - 64;
        uint16_t kh[8], kl[8];
        #pragma unroll
        for (int i = 0; i < 8; i++)
            split_bf16(qk_s[(8 + i) * QK_STR + nl], kh[i], kl[i]);
        uint32_t row[8];
        #pragma unroll
        for (int i = 0; i < 4; i++) {
            row[i]     = (uint32_t)kh[2*i] | ((uint32_t)kh[2*i+1] << 16);
            row[4 + i] = (uint32_t)kl[2*i] | ((uint32_t)kl[2*i+1] << 16);
        }
        uint4* kp = (uint4*)(g_kp + ((size_t)b * NSP + n0 + nl) * 8);
        kp[0] = ((uint4*)row)[0];
        kp[1] = ((uint4*)row)[1];
    }
}

// ---------------------------------------------------------------------------
// Split-KV flash attention with fused finisher-combine.
// Grid (32, 4, 2): the LAST CTA of each (b,qt) pair (atomic counter) reads the
// other split's partial from L2, adds its own (in smem), and writes out.
// ---------------------------------------------------------------------------
#define K_STR 48
#define V_STR 272
#define KBUF_SZ (128 * K_STR)
#define VBUF_SZ (64 * V_STR)
#define VBASE   (2 * KBUF_SZ)
#define SMEM_SZ (VBASE + 2 * VBUF_SZ)
#define STAGE_STR 132

__global__ __launch_bounds__(256) void attn_kernel(
    const float* __restrict__ x,
    const float* __restrict__ gamma,
    float* __restrict__ out)
{
    __shared__ __align__(16) char s_buf[SMEM_SZ];
    __shared__ float sl_s[128];
    __shared__ float sinv_s[128];
    __shared__ int s_old;

    const int tid  = threadIdx.x;
    const int wid  = tid >> 5;
    const int lane = tid & 31;
    const int g    = lane >> 2;
    const int tg   = lane & 3;
    const int b    = blockIdx.y;
    const int sp   = blockIdx.z;
    const int qt   = blockIdx.x;
    const int qbase = qt * 128;

    const uint32_t sbase = smem_u32(s_buf);

    const int mat      = lane >> 3;
    const int row_lane = lane & 7;
    const uint32_t k_lm_off = (uint32_t)(((mat >> 1) * 8 + row_lane) * K_STR + (mat & 1) * 16);
    const uint32_t v_lm_off = (uint32_t)(((mat >> 1) * 8 + row_lane) * V_STR + (mat & 1) * 16);

    uint32_t qh_r0, qh_r1, ql_r0, ql_r1;
    {
        const int r0 = qbase + wid * 16 + g;
        float2 q0 = *(const float2*)(g_q + ((size_t)b * NSP + r0) * 8 + tg * 2);
        float2 q1 = *(const float2*)(g_q + ((size_t)b * NSP + r0 + 8) * 8 + tg * 2);
        uint16_t h0, l0, h1, l1;
        split_bf16(q0.x, h0, l0); split_bf16(q0.y, h1, l1);
        qh_r0 = (uint32_t)h0 | ((uint32_t)h1 << 16);
        ql_r0 = (uint32_t)l0 | ((uint32_t)l1 << 16);
        split_bf16(q1.x, h0, l0); split_bf16(q1.y, h1, l1);
        qh_r1 = (uint32_t)h0 | ((uint32_t)h1 << 16);
        ql_r1 = (uint32_t)l0 | ((uint32_t)l1 << 16);
    }

    float oc[8][4];
    #pragma unroll
    for (int t = 0; t < 8; t++)
        #pragma unroll
        for (int i = 0; i < 4; i++) oc[t][i] = 0.f;
    float lsum0 = 0.f, lsum1 = 0.f;

    const uint32_t* gk = g_kp + (size_t)b * NSP * 8;
    const __nv_bfloat16* gv = g_v + (size_t)b * CCH * NSP;

    const int k_key  = tid >> 1;
    const int k_part = tid & 1;
    auto load_tile = [&](int kt, int buf) {
        cp_async16(sbase + buf * KBUF_SZ + k_key * K_STR + k_part * 16,
                   gk + ((size_t)kt * KT + k_key) * 8 + k_part * 4);
        #pragma unroll
        for (int i = 0; i < 4; i++) {
            int idx = tid + i * 256;
            int c = idx >> 4, seg = idx & 15;
            cp_async16(sbase + VBASE + buf * VBUF_SZ + c * V_STR + seg * 16,
                       gv + (size_t)c * NSP + kt * KT + seg * 8);
        }
    };

    const int kt0 = sp * TILES_PER_SPLIT;
    load_tile(kt0, 0);
    CP_COMMIT();

    for (int it = 0; it < TILES_PER_SPLIT; it++) {
        const int cur = it & 1;
        CP_WAIT0();
        __syncthreads();
        if (it + 1 < TILES_PER_SPLIT) {
            load_tile(kt0 + it + 1, cur ^ 1);
            CP_COMMIT();
        }

        const uint32_t k_lm = sbase + cur * KBUF_SZ + k_lm_off;
        const uint32_t v_lm = sbase + VBASE + cur * VBUF_SZ + v_lm_off;

        float sc[16][4];
        #pragma unroll
        for (int tp = 0; tp < 8; tp++) {
            uint32_t b00, b01, b10, b11;
            ldsm_x4(b00, b01, b10, b11, k_lm + (uint32_t)(tp * 16 * K_STR));
            const int t0 = 2 * tp, t1 = 2 * tp + 1;
            #pragma unroll
            for (int i = 0; i < 4; i++) { sc[t0][i] = 0.f; sc[t1][i] = 0.f; }
            mma_16x8x16(sc[t0], qh_r0, qh_r1, qh_r0, qh_r1, b00, b01);
            mma_16x8x8 (sc[t0], ql_r0, ql_r1, b00);
            mma_16x8x16(sc[t1], qh_r0, qh_r1, qh_r0, qh_r1, b10, b11);
            mma_16x8x8 (sc[t1], ql_r0, ql_r1, b10);
        }

        uint32_t pa[8][4];
        #pragma unroll
        for (int kk = 0; kk < 8; kk++) {
            float e00 = ex2f(sc[2*kk][0]),   e01 = ex2f(sc[2*kk][1]);
            float e02 = ex2f(sc[2*kk][2]),   e03 = ex2f(sc[2*kk][3]);
            float e10 = ex2f(sc[2*kk+1][0]), e11 = ex2f(sc[2*kk+1][1]);
            float e12 = ex2f(sc[2*kk+1][2]), e13 = ex2f(sc[2*kk+1][3]);
            lsum0 += (e00 + e01) + (e10 + e11);
            lsum1 += (e02 + e03) + (e12 + e13);
            pa[kk][0] = cvt_bf16x2(e01, e00);
            pa[kk][1] = cvt_bf16x2(e03, e02);
            pa[kk][2] = cvt_bf16x2(e11, e10);
            pa[kk][3] = cvt_bf16x2(e13, e12);
        }

        #pragma unroll
        for (int kk = 0; kk < 8; kk++) {
            #pragma unroll
            for (int tp = 0; tp < 4; tp++) {
                uint32_t b00, b01, b10, b11;
                ldsm_x4(b00, b01, b10, b11,
                        v_lm + (uint32_t)(tp * 16 * V_STR + kk * 32));
                mma_16x8x16(oc[2*tp],   pa[kk][0], pa[kk][1], pa[kk][2], pa[kk][3], b00, b01);
                mma_16x8x16(oc[2*tp+1], pa[kk][0], pa[kk][1], pa[kk][2], pa[kk][3], b10, b11);
            }
        }
    }

    // ---- reduce lsum; publish partials ----
    lsum0 += __shfl_xor_sync(0xFFFFFFFF, lsum0, 1);
    lsum0 += __shfl_xor_sync(0xFFFFFFFF, lsum0, 2);
    lsum1 += __shfl_xor_sync(0xFFFFFFFF, lsum1, 1);
    lsum1 += __shfl_xor_sync(0xFFFFFFFF, lsum1, 2);
    const int pbase = ((sp * BATCH + b) * NQT + qt);
    if (tg == 0) {
        g_pl[pbase * 128 + wid * 16 + g]     = lsum0;
        g_pl[pbase * 128 + wid * 16 + g + 8] = lsum1;
        sl_s[wid * 16 + g]     = lsum0;
        sl_s[wid * 16 + g + 8] = lsum1;
    }

    __syncthreads();                       // tile reads done; reuse s_buf
    float* stage = (float*)s_buf;          // [64][STAGE_STR] unnormalized O
    const int n0 = wid * 16 + g;
    #pragma unroll
    for (int t = 0; t < 8; t++) {
        const int c = t * 8 + tg * 2;
        stage[c * STAGE_STR + n0]           = oc[t][0];
        stage[(c + 1) * STAGE_STR + n0]     = oc[t][1];
        stage[c * STAGE_STR + n0 + 8]       = oc[t][2];
        stage[(c + 1) * STAGE_STR + n0 + 8] = oc[t][3];
    }
    __syncthreads();

    float* po = g_po + (size_t)pbase * (CCH * 128);
    for (int idx = tid; idx < CCH * 128; idx += 256) {
        const int c  = idx >> 7;
        const int nn = idx & 127;
        po[idx] = stage[c * STAGE_STR + nn];
    }

    // ---- finisher election (threadfence + atomic, self-resetting) ----
    __threadfence();
    __syncthreads();
    if (tid == 0) s_old = atomicAdd(&g_sem[b * NQT + qt], 1);
    __syncthreads();
    if (s_old == 0) return;                // first CTA: partial published, done
    if (tid == 0) g_sem[b * NQT + qt] = 0; // reset for next graph replay

    // ---- combine: own (smem) + other (L2), normalize, residual write ----
    const int pother = (((sp ^ 1) * BATCH + b) * NQT + qt);
    if (tid < 128)
        sinv_s[tid] = __ldg(gamma) / (sl_s[tid] + g_pl[pother * 128 + tid]);
    __syncthreads();

    const float* poo = g_po + (size_t)pother * (CCH * 128);
    const size_t base = (size_t)b * CCH * NSP + (size_t)qt * 128;
    for (int idx = tid; idx < CCH * 128; idx += 256) {
        const int c  = idx >> 7;
        const int nn = idx & 127;
        const size_t off = base + (size_t)c * NSP + nn;
        out[off] = x[off] + (stage[c * STAGE_STR + nn] + poo[idx]) * sinv_s[nn];
    }
}

extern "C" void kernel_launch(void* const* d_in, const int* in_sizes, int n_in,
                              void* d_out, int out_size)
{
    const float* x     = (const float*)d_in[0];
    const float* wq    = (const float*)d_in[1];
    const float* bq    = (const float*)d_in[2];
    const float* wk    = (const float*)d_in[3];
    const float* bk    = (const float*)d_in[4];
    const float* wv    = (const float*)d_in[5];
    const float* bv    = (const float*)d_in[6];
    const float* gamma = (const float*)d_in[7];
    float* out = (float*)d_out;

    dim3 pg(NSP / 64, BATCH);
    proj_kernel<<<pg, 256>>>(x, wq, bq, wk, bk, wv, bv);

    dim3 ag(NQT, BATCH, NSPLIT);
    attn_kernel<<<ag, 256>>>(x, gamma, out);
}

// round 15
// speedup vs baseline: 1.1230x; 1.0159x over previous
#include <cuda_runtime.h>
#include <cuda_bf16.h>
#include <stdint.h>

#define NSP   4096
#define CCH   64
#define BATCH 4
#define KT    128
#define NTILES (NSP / KT)
#define NQT   (NSP / 128)      // 32 q-tiles
#define NSPLIT 2
#define TILES_PER_SPLIT (NTILES / NSPLIT)

// ---------------------------------------------------------------------------
// Scratch
// ---------------------------------------------------------------------------
__device__ float         g_q [BATCH * NSP * 8];
__device__ uint32_t      g_kp[BATCH * NSP * 8];
__device__ __nv_bfloat16 g_v [(size_t)BATCH * CCH * NSP];
__device__ float         g_po[(size_t)NSPLIT * BATCH * NQT * CCH * 128];
__device__ float         g_pl[NSPLIT * BATCH * NQT * 128];
__device__ int           g_sem[BATCH * NQT];   // zero-init; self-resetting

#define LOG2E 1.4426950408889634f

__device__ __forceinline__ void mma_16x8x16(
    float c[4], uint32_t a0, uint32_t a1, uint32_t a2, uint32_t a3,
    uint32_t b0, uint32_t b1)
{
    asm volatile(
        "mma.sync.aligned.m16n8k16.row.col.f32.bf16.bf16.f32 "
        "{%0,%1,%2,%3}, {%4,%5,%6,%7}, {%8,%9}, {%0,%1,%2,%3};"
        : "+f"(c[0]), "+f"(c[1]), "+f"(c[2]), "+f"(c[3])
        : "r"(a0), "r"(a1), "r"(a2), "r"(a3), "r"(b0), "r"(b1));
}
__device__ __forceinline__ void mma_16x8x8(
    float c[4], uint32_t a0, uint32_t a1, uint32_t b0)
{
    asm volatile(
        "mma.sync.aligned.m16n8k8.row.col.f32.bf16.bf16.f32 "
        "{%0,%1,%2,%3}, {%4,%5}, {%6}, {%0,%1,%2,%3};"
        : "+f"(c[0]), "+f"(c[1]), "+f"(c[2]), "+f"(c[3])
        : "r"(a0), "r"(a1), "r"(b0));
}
__device__ __forceinline__ void ldsm_x4(
    uint32_t& r0, uint32_t& r1, uint32_t& r2, uint32_t& r3, uint32_t addr)
{
    asm volatile("ldmatrix.sync.aligned.m8n8.x4.shared.b16 {%0,%1,%2,%3}, [%4];"
        : "=r"(r0), "=r"(r1), "=r"(r2), "=r"(r3) : "r"(addr));
}
__device__ __forceinline__ void ldsm_x4_t(
    uint32_t& r0, uint32_t& r1, uint32_t& r2, uint32_t& r3, uint32_t addr)
{
    asm volatile("ldmatrix.sync.aligned.m8n8.x4.trans.shared.b16 {%0,%1,%2,%3}, [%4];"
        : "=r"(r0), "=r"(r1), "=r"(r2), "=r"(r3) : "r"(addr));
}
__device__ __forceinline__ uint32_t cvt_bf16x2(float hi, float lo) {
    uint32_t r;
    asm("cvt.rn.bf16x2.f32 %0, %1, %2;" : "=r"(r) : "f"(hi), "f"(lo));
    return r;
}
__device__ __forceinline__ float ex2f(float x) {
    float r;
    asm("ex2.approx.f32 %0, %1;" : "=f"(r) : "f"(x));
    return r;
}
__device__ __forceinline__ void split_bf16(float v, uint16_t& h, uint16_t& l) {
    __nv_bfloat16 hb = __float2bfloat16(v);
    __nv_bfloat16 lb = __float2bfloat16(v - __bfloat162float(hb));
    h = __bfloat16_as_ushort(hb);
    l = __bfloat16_as_ushort(lb);
}
__device__ __forceinline__ uint32_t smem_u32(const void* p) {
    uint32_t a;
    asm("{ .reg .u64 t; cvta.to.shared.u64 t, %1; cvt.u32.u64 %0, t; }"
        : "=r"(a) : "l"(p));
    return a;
}
__device__ __forceinline__ void cp_async16(uint32_t dst, const void* src) {
    asm volatile("cp.async.cg.shared.global [%0], [%1], 16;"
                 :: "r"(dst), "l"(src));
}
#define CP_COMMIT() asm volatile("cp.async.commit_group;" ::: "memory")
#define CP_WAIT0()  asm volatile("cp.async.wait_group 0;" ::: "memory")

// ---------------------------------------------------------------------------
// Projection v7b (unchanged): tensor-core GEMM, ldmatrix-aligned strides.
// ---------------------------------------------------------------------------
#define WS_STR 72
#define XT_STR 72
#define QK_STR 68

__global__ __launch_bounds__(256) void proj_kernel(
    const float* __restrict__ x,
    const float* __restrict__ wq, const float* __restrict__ bq,
    const float* __restrict__ wk, const float* __restrict__ bk,
    const float* __restrict__ wv, const float* __restrict__ bv)
{
    __shared__ __align__(16) uint16_t wh_s[80 * WS_STR];
    __shared__ __align__(16) uint16_t wl_s[80 * WS_STR];
    __shared__ __align__(16) uint16_t xh_s[64 * XT_STR];
    __shared__ __align__(16) uint16_t xl_s[64 * XT_STR];
    __shared__ __align__(16) float    qk_s[16 * QK_STR];
    __shared__ float b_s[80];

    const int tid  = threadIdx.x;
    const int lane = tid & 31;
    const int wrp  = tid >> 5;
    const int g    = lane >> 2;
    const int tg   = lane & 3;
    const int b    = blockIdx.y;
    const int n0   = blockIdx.x * 64;

    #pragma unroll
    for (int i = 0; i < 10; i++) {
        int idx = tid + i * 256;
        int o = idx >> 5, c = (idx & 31) * 2;
        float2 w2;
        if (o < 8)       w2 = *(const float2*)(wq + o * 64 + c);
        else if (o < 16) w2 = *(const float2*)(wk + (o - 8) * 64 + c);
        else             w2 = *(const float2*)(wv + (o - 16) * 64 + c);
        uint16_t h0, l0, h1, l1;
        split_bf16(w2.x, h0, l0); split_bf16(w2.y, h1, l1);
        *(uint32_t*)(wh_s + o * WS_STR + c) = (uint32_t)h0 | ((uint32_t)h1 << 16);
        *(uint32_t*)(wl_s + o * WS_STR + c) = (uint32_t)l0 | ((uint32_t)l1 << 16);
    }
    if (tid < 8)       b_s[tid] = bq[tid];
    else if (tid < 16) b_s[tid] = bk[tid - 8];
    else if (tid < 80) b_s[tid] = bv[tid - 16];

    {
        const float* xb = x + (size_t)b * CCH * NSP + n0;
        #pragma unroll
        for (int i = 0; i < 4; i++) {
            int idx = tid + i * 256;
            int c = idx >> 4, nq = (idx & 15) * 4;
            float4 v = *(const float4*)(xb + (size_t)c * NSP + nq);
            uint16_t h0, l0, h1, l1, h2, l2, h3, l3;
            split_bf16(v.x, h0, l0); split_bf16(v.y, h1, l1);
            split_bf16(v.z, h2, l2); split_bf16(v.w, h3, l3);
            *(uint32_t*)(xh_s + c * XT_STR + nq)     = (uint32_t)h0 | ((uint32_t)h1 << 16);
            *(uint32_t*)(xh_s + c * XT_STR + nq + 2) = (uint32_t)h2 | ((uint32_t)h3 << 16);
            *(uint32_t*)(xl_s + c * XT_STR + nq)     = (uint32_t)l0 | ((uint32_t)l1 << 16);
            *(uint32_t*)(xl_s + c * XT_STR + nq + 2) = (uint32_t)l2 | ((uint32_t)l3 << 16);
        }
    }
    __syncthreads();

    const int lm_m  = lane >> 3;
    const int lm_rl = lane & 7;
    const uint32_t wh_base = smem_u32(wh_s);
    const uint32_t wl_base = smem_u32(wl_s);
    const uint32_t xh_base = smem_u32(xh_s);
    const uint32_t xl_base = smem_u32(xl_s);
    const uint32_t a_off = (uint32_t)((((lm_m & 1) * 8 + lm_rl) * WS_STR + (lm_m >> 1) * 8) * 2);
    const uint32_t b_off = (uint32_t)((((lm_m & 1) * 8 + lm_rl + (lm_m >> 1) * 16) * XT_STR + wrp * 8) * 2);

    float C[5][4];
    #pragma unroll
    for (int mt = 0; mt < 5; mt++)
        #pragma unroll
        for (int i = 0; i < 4; i++) C[mt][i] = 0.f;

    #pragma unroll
    for (int kp = 0; kp < 2; kp++) {
        uint32_t bh[2][2], bl[2][2];
        ldsm_x4_t(bh[0][0], bh[0][1], bh[1][0], bh[1][1],
                  xh_base + b_off + (uint32_t)(32 * kp * XT_STR * 2));
        ldsm_x4_t(bl[0][0], bl[0][1], bl[1][0], bl[1][1],
                  xl_base + b_off + (uint32_t)(32 * kp * XT_STR * 2));
        #pragma unroll
        for (int kk = 0; kk < 2; kk++) {
            const int ks = 2 * kp + kk;
            #pragma unroll
            for (int mt = 0; mt < 5; mt++) {
                const uint32_t astep = (uint32_t)((16 * mt * WS_STR + 16 * ks) * 2);
                uint32_t ah0, ah1, ah2, ah3, al0, al1, al2, al3;
                ldsm_x4(ah0, ah1, ah2, ah3, wh_base + a_off + astep);
                ldsm_x4(al0, al1, al2, al3, wl_base + a_off + astep);
                mma_16x8x16(C[mt], ah0, ah1, ah2, ah3, bh[kk][0], bh[kk][1]);
                mma_16x8x16(C[mt], ah0, ah1, ah2, ah3, bl[kk][0], bl[kk][1]);
                mma_16x8x16(C[mt], al0, al1, al2, al3, bh[kk][0], bh[kk][1]);
            }
        }
    }

    #pragma unroll
    for (int mt = 0; mt < 5; mt++) {
        const float blo = b_s[16 * mt + g];
        const float bhi = b_s[16 * mt + g + 8];
        C[mt][0] += blo; C[mt][1] += blo;
        C[mt][2] += bhi; C[mt][3] += bhi;
    }

    __nv_bfloat16* vb = g_v + (size_t)b * CCH * NSP;
    const int nv = n0 + wrp * 8 + 2 * tg;
    #pragma unroll
    for (int mt = 1; mt < 5; mt++) {
        const int ch = 16 * mt + g - 16;
        *(uint32_t*)(vb + (size_t)ch * NSP + nv)       = cvt_bf16x2(C[mt][1], C[mt][0]);
        *(uint32_t*)(vb + (size_t)(ch + 8) * NSP + nv) = cvt_bf16x2(C[mt][3], C[mt][2]);
    }

    {
        const int nl = wrp * 8 + 2 * tg;
        *(float2*)(qk_s + g * QK_STR + nl)       = make_float2(C[0][0], C[0][1]);
        *(float2*)(qk_s + (g + 8) * QK_STR + nl) = make_float2(C[0][2], C[0][3]);
    }
    __syncthreads();

    if (tid < 64) {
        const int nl = tid;
        float* qp = g_q + ((size_t)b * NSP + n0 + nl) * 8;
        float4 q0, q1;
        q0.x = qk_s[0 * QK_STR + nl] * LOG2E;
        q0.y = qk_s[1 * QK_STR + nl] * LOG2E;
        q0.z = qk_s[2 * QK_STR + nl] * LOG2E;
        q0.w = qk_s[3 * QK_STR + nl] * LOG2E;
        q1.x = qk_s[4 * QK_STR + nl] * LOG2E;
        q1.y = qk_s[5 * QK_STR + nl] * LOG2E;
        q1.z = qk_s[6 * QK_STR + nl] * LOG2E;
        q1.w = qk_s[7 * QK_STR + nl] * LOG2E;
        ((float4*)qp)[0] = q0;
        ((float4*)qp)[1] = q1;
    } else if (tid < 128) {
        const int nl = tid - 64;
        uint16_t kh[8], kl[8];
        #pragma unroll
        for (int i = 0; i < 8; i++)
            split_bf16(qk_s[(8 + i) * QK_STR + nl], kh[i], kl[i]);
        uint32_t row[8];
        #pragma unroll
        for (int i = 0; i < 4; i++) {
            row[i]     = (uint32_t)kh[2*i] | ((uint32_t)kh[2*i+1] << 16);
            row[4 + i] = (uint32_t)kl[2*i] | ((uint32_t)kl[2*i+1] << 16);
        }
        uint4* kp = (uint4*)(g_kp + ((size_t)b * NSP + n0 + nl) * 8);
        kp[0] = ((uint4*)row)[0];
        kp[1] = ((uint4*)row)[1];
    }
}

// ---------------------------------------------------------------------------
// Split-KV flash attention, chunk-pipelined softmax (overlap MUFU with tensor)
// + fused finisher-combine. Grid (32, 4, 2) x 256.
// Per tile: 4 chunks of 32 keys; issue order S(c+1), O(c), E(c+1) so MMA2 of
// chunk c fills the tensor pipe while exp of chunk c+1 runs on MUFU.
// ---------------------------------------------------------------------------
#define K_STR 48
#define V_STR 272
#define KBUF_SZ (128 * K_STR)
#define VBUF_SZ (64 * V_STR)
#define VBASE   (2 * KBUF_SZ)
#define SMEM_SZ (VBASE + 2 * VBUF_SZ)
#define STAGE_STR 132

__global__ __launch_bounds__(256) void attn_kernel(
    const float* __restrict__ x,
    const float* __restrict__ gamma,
    float* __restrict__ out)
{
    __shared__ __align__(16) char s_buf[SMEM_SZ];
    __shared__ float sl_s[128];
    __shared__ float sinv_s[128];
    __shared__ int s_old;

    const int tid  = threadIdx.x;
    const int wid  = tid >> 5;
    const int lane = tid & 31;
    const int g    = lane >> 2;
    const int tg   = lane & 3;
    const int b    = blockIdx.y;
    const int sp   = blockIdx.z;
    const int qt   = blockIdx.x;
    const int qbase = qt * 128;

    const uint32_t sbase = smem_u32(s_buf);

    const int mat      = lane >> 3;
    const int row_lane = lane & 7;
    const uint32_t k_lm_off = (uint32_t)(((mat >> 1) * 8 + row_lane) * K_STR + (mat & 1) * 16);
    const uint32_t v_lm_off = (uint32_t)(((mat >> 1) * 8 + row_lane) * V_STR + (mat & 1) * 16);

    uint32_t qh_r0, qh_r1, ql_r0, ql_r1;
    {
        const int r0 = qbase + wid * 16 + g;
        float2 q0 = *(const float2*)(g_q + ((size_t)b * NSP + r0) * 8 + tg * 2);
        float2 q1 = *(const float2*)(g_q + ((size_t)b * NSP + r0 + 8) * 8 + tg * 2);
        uint16_t h0, l0, h1, l1;
        split_bf16(q0.x, h0, l0); split_bf16(q0.y, h1, l1);
        qh_r0 = (uint32_t)h0 | ((uint32_t)h1 << 16);
        ql_r0 = (uint32_t)l0 | ((uint32_t)l1 << 16);
        split_bf16(q1.x, h0, l0); split_bf16(q1.y, h1, l1);
        qh_r1 = (uint32_t)h0 | ((uint32_t)h1 << 16);
        ql_r1 = (uint32_t)l0 | ((uint32_t)l1 << 16);
    }

    float oc[8][4];
    #pragma unroll
    for (int t = 0; t < 8; t++)
        #pragma unroll
        for (int i = 0; i < 4; i++) oc[t][i] = 0.f;
    float lsum0 = 0.f, lsum1 = 0.f;

    const uint32_t* gk = g_kp + (size_t)b * NSP * 8;
    const __nv_bfloat16* gv = g_v + (size_t)b * CCH * NSP;

    const int k_key  = tid >> 1;
    const int k_part = tid & 1;
    auto load_tile = [&](int kt, int buf) {
        cp_async16(sbase + buf * KBUF_SZ + k_key * K_STR + k_part * 16,
                   gk + ((size_t)kt * KT + k_key) * 8 + k_part * 4);
        #pragma unroll
        for (int i = 0; i < 4; i++) {
            int idx = tid + i * 256;
            int c = idx >> 4, seg = idx & 15;
            cp_async16(sbase + VBASE + buf * VBUF_SZ + c * V_STR + seg * 16,
                       gv + (size_t)c * NSP + kt * KT + seg * 8);
        }
    };

    const int kt0 = sp * TILES_PER_SPLIT;
    load_tile(kt0, 0);
    CP_COMMIT();

    for (int it = 0; it < TILES_PER_SPLIT; it++) {
        const int cur = it & 1;
        CP_WAIT0();
        __syncthreads();
        if (it + 1 < TILES_PER_SPLIT) {
            load_tile(kt0 + it + 1, cur ^ 1);
            CP_COMMIT();
        }

        const uint32_t k_lm = sbase + cur * KBUF_SZ + k_lm_off;
        const uint32_t v_lm = sbase + VBASE + cur * VBUF_SZ + v_lm_off;

        // chunk score / pack double buffers
        float    sc[2][4][4];
        uint32_t pa[2][2][4];

        // S(c): scores for chunk c (keys 32c..32c+31 -> local t 0..3)
        auto S = [&](int c, float scc[4][4]) {
            #pragma unroll
            for (int i = 0; i < 2; i++) {
                const int tp = 2 * c + i;
                uint32_t b00, b01, b10, b11;
                ldsm_x4(b00, b01, b10, b11, k_lm + (uint32_t)(tp * 16 * K_STR));
                #pragma unroll
                for (int j = 0; j < 4; j++) { scc[2*i][j] = 0.f; scc[2*i+1][j] = 0.f; }
                mma_16x8x16(scc[2*i],   qh_r0, qh_r1, qh_r0, qh_r1, b00, b01);
                mma_16x8x8 (scc[2*i],   ql_r0, ql_r1, b00);
                mma_16x8x16(scc[2*i+1], qh_r0, qh_r1, qh_r0, qh_r1, b10, b11);
                mma_16x8x8 (scc[2*i+1], ql_r0, ql_r1, b10);
            }
        };
        // E(c): exp + pack chunk c
        auto E = [&](float scc[4][4], uint32_t pac[2][4]) {
            #pragma unroll
            for (int i = 0; i < 2; i++) {
                float e00 = ex2f(scc[2*i][0]),   e01 = ex2f(scc[2*i][1]);
                float e02 = ex2f(scc[2*i][2]),   e03 = ex2f(scc[2*i][3]);
                float e10 = ex2f(scc[2*i+1][0]), e11 = ex2f(scc[2*i+1][1]);
                float e12 = ex2f(scc[2*i+1][2]), e13 = ex2f(scc[2*i+1][3]);
                lsum0 += (e00 + e01) + (e10 + e11);
                lsum1 += (e02 + e03) + (e12 + e13);
                pac[i][0] = cvt_bf16x2(e01, e00);
                pac[i][1] = cvt_bf16x2(e03, e02);
                pac[i][2] = cvt_bf16x2(e11, e10);
                pac[i][3] = cvt_bf16x2(e13, e12);
            }
        };
        // O(c): accumulate chunk c into output
        auto O = [&](int c, uint32_t pac[2][4]) {
            #pragma unroll
            for (int i = 0; i < 2; i++) {
                const int kk = 2 * c + i;
                #pragma unroll
                for (int tp = 0; tp < 4; tp++) {
                    uint32_t b00, b01, b10, b11;
                    ldsm_x4(b00, b01, b10, b11,
                            v_lm + (uint32_t)(tp * 16 * V_STR + kk * 32));
                    mma_16x8x16(oc[2*tp],   pac[i][0], pac[i][1], pac[i][2], pac[i][3], b00, b01);
                    mma_16x8x16(oc[2*tp+1], pac[i][0], pac[i][1], pac[i][2], pac[i][3], b10, b11);
                }
            }
        };

        // pipelined chunk loop: S(c+1) queued, O(c) fills tensor, E(c+1) on MUFU
        S(0, sc[0]);
        E(sc[0], pa[0]);
        #pragma unroll
        for (int c = 0; c < 4; c++) {
            const int curp = c & 1, nxt = curp ^ 1;
            if (c < 3) S(c + 1, sc[nxt]);
            O(c, pa[curp]);
            if (c < 3) E(sc[nxt], pa[nxt]);
        }
    }

    // ---- reduce lsum; publish partials ----
    lsum0 += __shfl_xor_sync(0xFFFFFFFF, lsum0, 1);
    lsum0 += __shfl_xor_sync(0xFFFFFFFF, lsum0, 2);
    lsum1 += __shfl_xor_sync(0xFFFFFFFF, lsum1, 1);
    lsum1 += __shfl_xor_sync(0xFFFFFFFF, lsum1, 2);
    const int pbase = ((sp * BATCH + b) * NQT + qt);
    if (tg == 0) {
        g_pl[pbase * 128 + wid * 16 + g]     = lsum0;
        g_pl[pbase * 128 + wid * 16 + g + 8] = lsum1;
        sl_s[wid * 16 + g]     = lsum0;
        sl_s[wid * 16 + g + 8] = lsum1;
    }

    __syncthreads();                       // tile reads done; reuse s_buf
    float* stage = (float*)s_buf;          // [64][STAGE_STR] unnormalized O
    const int n0 = wid * 16 + g;
    #pragma unroll
    for (int t = 0; t < 8; t++) {
        const int c = t * 8 + tg * 2;
        stage[c * STAGE_STR + n0]           = oc[t][0];
        stage[(c + 1) * STAGE_STR + n0]     = oc[t][1];
        stage[c * STAGE_STR + n0 + 8]       = oc[t][2];
        stage[(c + 1) * STAGE_STR + n0 + 8] = oc[t][3];
    }
    __syncthreads();

    float* po = g_po + (size_t)pbase * (CCH * 128);
    for (int idx = tid; idx < CCH * 128; idx += 256) {
        const int c  = idx >> 7;
        const int nn = idx & 127;
        po[idx] = stage[c * STAGE_STR + nn];
    }

    // ---- finisher election (threadfence + atomic, self-resetting) ----
    __threadfence();
    __syncthreads();
    if (tid == 0) s_old = atomicAdd(&g_sem[b * NQT + qt], 1);
    __syncthreads();
    if (s_old == 0) return;                // first CTA done
    if (tid == 0) g_sem[b * NQT + qt] = 0; // reset for graph replay

    // ---- combine: own (smem) + other (L2), normalize, residual write ----
    const int pother = (((sp ^ 1) * BATCH + b) * NQT + qt);
    if (tid < 128)
        sinv_s[tid] = __ldg(gamma) / (sl_s[tid] + g_pl[pother * 128 + tid]);
    __syncthreads();

    const float* poo = g_po + (size_t)pother * (CCH * 128);
    const size_t base = (size_t)b * CCH * NSP + (size_t)qt * 128;
    for (int idx = tid; idx < CCH * 128; idx += 256) {
        const int c  = idx >> 7;
        const int nn = idx & 127;
        const size_t off = base + (size_t)c * NSP + nn;
        out[off] = x[off] + (stage[c * STAGE_STR + nn] + poo[idx]) * sinv_s[nn];
    }
}

extern "C" void kernel_launch(void* const* d_in, const int* in_sizes, int n_in,
                              void* d_out, int out_size)
{
    const float* x     = (const float*)d_in[0];
    const float* wq    = (const float*)d_in[1];
    const float* bq    = (const float*)d_in[2];
    const float* wk    = (const float*)d_in[3];
    const float* bk    = (const float*)d_in[4];
    const float* wv    = (const float*)d_in[5];
    const float* bv    = (const float*)d_in[6];
    const float* gamma = (const float*)d_in[7];
    float* out = (float*)d_out;

    dim3 pg(NSP / 64, BATCH);
    proj_kernel<<<pg, 256>>>(x, wq, bq, wk, bk, wv, bv);

    dim3 ag(NQT, BATCH, NSPLIT);
    attn_kernel<<<ag, 256>>>(x, gamma, out);
}

// round 16
// speedup vs baseline: 1.1326x; 1.0085x over previous
#include <cuda_runtime.h>
#include <cuda_bf16.h>
#include <stdint.h>

#define NSP   4096
#define CCH   64
#define BATCH 4
#define KT    128
#define NTILES (NSP / KT)
#define NQT   (NSP / 128)      // 32 q-tiles
#define NSPLIT 4
#define TILES_PER_SPLIT (NTILES / NSPLIT)

// ---------------------------------------------------------------------------
// Scratch
// ---------------------------------------------------------------------------
__device__ float         g_q [BATCH * NSP * 8];
__device__ uint32_t      g_kp[BATCH * NSP * 8];
__device__ __nv_bfloat16 g_v [(size_t)BATCH * CCH * NSP];
__device__ float         g_po[(size_t)NSPLIT * BATCH * NQT * CCH * 128];
__device__ float         g_pl[NSPLIT * BATCH * NQT * 128];
__device__ int           g_sem[BATCH * NQT];   // zero-init; self-resetting

#define LOG2E 1.4426950408889634f

__device__ __forceinline__ void mma_16x8x16(
    float c[4], uint32_t a0, uint32_t a1, uint32_t a2, uint32_t a3,
    uint32_t b0, uint32_t b1)
{
    asm volatile(
        "mma.sync.aligned.m16n8k16.row.col.f32.bf16.bf16.f32 "
        "{%0,%1,%2,%3}, {%4,%5,%6,%7}, {%8,%9}, {%0,%1,%2,%3};"
        : "+f"(c[0]), "+f"(c[1]), "+f"(c[2]), "+f"(c[3])
        : "r"(a0), "r"(a1), "r"(a2), "r"(a3), "r"(b0), "r"(b1));
}
__device__ __forceinline__ void mma_16x8x8(
    float c[4], uint32_t a0, uint32_t a1, uint32_t b0)
{
    asm volatile(
        "mma.sync.aligned.m16n8k8.row.col.f32.bf16.bf16.f32 "
        "{%0,%1,%2,%3}, {%4,%5}, {%6}, {%0,%1,%2,%3};"
        : "+f"(c[0]), "+f"(c[1]), "+f"(c[2]), "+f"(c[3])
        : "r"(a0), "r"(a1), "r"(b0));
}
__device__ __forceinline__ void ldsm_x4(
    uint32_t& r0, uint32_t& r1, uint32_t& r2, uint32_t& r3, uint32_t addr)
{
    asm volatile("ldmatrix.sync.aligned.m8n8.x4.shared.b16 {%0,%1,%2,%3}, [%4];"
        : "=r"(r0), "=r"(r1), "=r"(r2), "=r"(r3) : "r"(addr));
}
__device__ __forceinline__ void ldsm_x4_t(
    uint32_t& r0, uint32_t& r1, uint32_t& r2, uint32_t& r3, uint32_t addr)
{
    asm volatile("ldmatrix.sync.aligned.m8n8.x4.trans.shared.b16 {%0,%1,%2,%3}, [%4];"
        : "=r"(r0), "=r"(r1), "=r"(r2), "=r"(r3) : "r"(addr));
}
__device__ __forceinline__ uint32_t cvt_bf16x2(float hi, float lo) {
    uint32_t r;
    asm("cvt.rn.bf16x2.f32 %0, %1, %2;" : "=r"(r) : "f"(hi), "f"(lo));
    return r;
}
__device__ __forceinline__ float ex2f(float x) {
    float r;
    asm("ex2.approx.f32 %0, %1;" : "=f"(r) : "f"(x));
    return r;
}
__device__ __forceinline__ void split_bf16(float v, uint16_t& h, uint16_t& l) {
    __nv_bfloat16 hb = __float2bfloat16(v);
    __nv_bfloat16 lb = __float2bfloat16(v - __bfloat162float(hb));
    h = __bfloat16_as_ushort(hb);
    l = __bfloat16_as_ushort(lb);
}
__device__ __forceinline__ uint32_t smem_u32(const void* p) {
    uint32_t a;
    asm("{ .reg .u64 t; cvta.to.shared.u64 t, %1; cvt.u32.u64 %0, t; }"
        : "=r"(a) : "l"(p));
    return a;
}
__device__ __forceinline__ void cp_async16(uint32_t dst, const void* src) {
    asm volatile("cp.async.cg.shared.global [%0], [%1], 16;"
                 :: "r"(dst), "l"(src));
}
#define CP_COMMIT() asm volatile("cp.async.commit_group;" ::: "memory")
#define CP_WAIT0()  asm volatile("cp.async.wait_group 0;" ::: "memory")

// ---------------------------------------------------------------------------
// Projection v7b (unchanged): tensor-core GEMM, ldmatrix-aligned strides.
// ---------------------------------------------------------------------------
#define WS_STR 72
#define XT_STR 72
#define QK_STR 68

__global__ __launch_bounds__(256) void proj_kernel(
    const float* __restrict__ x,
    const float* __restrict__ wq, const float* __restrict__ bq,
    const float* __restrict__ wk, const float* __restrict__ bk,
    const float* __restrict__ wv, const float* __restrict__ bv)
{
    __shared__ __align__(16) uint16_t wh_s[80 * WS_STR];
    __shared__ __align__(16) uint16_t wl_s[80 * WS_STR];
    __shared__ __align__(16) uint16_t xh_s[64 * XT_STR];
    __shared__ __align__(16) uint16_t xl_s[64 * XT_STR];
    __shared__ __align__(16) float    qk_s[16 * QK_STR];
    __shared__ float b_s[80];

    const int tid  = threadIdx.x;
    const int lane = tid & 31;
    const int wrp  = tid >> 5;
    const int g    = lane >> 2;
    const int tg   = lane & 3;
    const int b    = blockIdx.y;
    const int n0   = blockIdx.x * 64;

    #pragma unroll
    for (int i = 0; i < 10; i++) {
        int idx = tid + i * 256;
        int o = idx >> 5, c = (idx & 31) * 2;
        float2 w2;
        if (o < 8)       w2 = *(const float2*)(wq + o * 64 + c);
        else if (o < 16) w2 = *(const float2*)(wk + (o - 8) * 64 + c);
        else             w2 = *(const float2*)(wv + (o - 16) * 64 + c);
        uint16_t h0, l0, h1, l1;
        split_bf16(w2.x, h0, l0); split_bf16(w2.y, h1, l1);
        *(uint32_t*)(wh_s + o * WS_STR + c) = (uint32_t)h0 | ((uint32_t)h1 << 16);
        *(uint32_t*)(wl_s + o * WS_STR + c) = (uint32_t)l0 | ((uint32_t)l1 << 16);
    }
    if (tid < 8)       b_s[tid] = bq[tid];
    else if (tid < 16) b_s[tid] = bk[tid - 8];
    else if (tid < 80) b_s[tid] = bv[tid - 16];

    {
        const float* xb = x + (size_t)b * CCH * NSP + n0;
        #pragma unroll
        for (int i = 0; i < 4; i++) {
            int idx = tid + i * 256;
            int c = idx >> 4, nq = (idx & 15) * 4;
            float4 v = *(const float4*)(xb + (size_t)c * NSP + nq);
            uint16_t h0, l0, h1, l1, h2, l2, h3, l3;
            split_bf16(v.x, h0, l0); split_bf16(v.y, h1, l1);
            split_bf16(v.z, h2, l2); split_bf16(v.w, h3, l3);
            *(uint32_t*)(xh_s + c * XT_STR + nq)     = (uint32_t)h0 | ((uint32_t)h1 << 16);
            *(uint32_t*)(xh_s + c * XT_STR + nq + 2) = (uint32_t)h2 | ((uint32_t)h3 << 16);
            *(uint32_t*)(xl_s + c * XT_STR + nq)     = (uint32_t)l0 | ((uint32_t)l1 << 16);
            *(uint32_t*)(xl_s + c * XT_STR + nq + 2) = (uint32_t)l2 | ((uint32_t)l3 << 16);
        }
    }
    __syncthreads();

    const int lm_m  = lane >> 3;
    const int lm_rl = lane & 7;
    const uint32_t wh_base = smem_u32(wh_s);
    const uint32_t wl_base = smem_u32(wl_s);
    const uint32_t xh_base = smem_u32(xh_s);
    const uint32_t xl_base = smem_u32(xl_s);
    const uint32_t a_off = (uint32_t)((((lm_m & 1) * 8 + lm_rl) * WS_STR + (lm_m >> 1) * 8) * 2);
    const uint32_t b_off = (uint32_t)((((lm_m & 1) * 8 + lm_rl + (lm_m >> 1) * 16) * XT_STR + wrp * 8) * 2);

    float C[5][4];
    #pragma unroll
    for (int mt = 0; mt < 5; mt++)
        #pragma unroll
        for (int i = 0; i < 4; i++) C[mt][i] = 0.f;

    #pragma unroll
    for (int kp = 0; kp < 2; kp++) {
        uint32_t bh[2][2], bl[2][2];
        ldsm_x4_t(bh[0][0], bh[0][1], bh[1][0], bh[1][1],
                  xh_base + b_off + (uint32_t)(32 * kp * XT_STR * 2));
        ldsm_x4_t(bl[0][0], bl[0][1], bl[1][0], bl[1][1],
                  xl_base + b_off + (uint32_t)(32 * kp * XT_STR * 2));
        #pragma unroll
        for (int kk = 0; kk < 2; kk++) {
            const int ks = 2 * kp + kk;
            #pragma unroll
            for (int mt = 0; mt < 5; mt++) {
                const uint32_t astep = (uint32_t)((16 * mt * WS_STR + 16 * ks) * 2);
                uint32_t ah0, ah1, ah2, ah3, al0, al1, al2, al3;
                ldsm_x4(ah0, ah1, ah2, ah3, wh_base + a_off + astep);
                ldsm_x4(al0, al1, al2, al3, wl_base + a_off + astep);
                mma_16x8x16(C[mt], ah0, ah1, ah2, ah3, bh[kk][0], bh[kk][1]);
                mma_16x8x16(C[mt], ah0, ah1, ah2, ah3, bl[kk][0], bl[kk][1]);
                mma_16x8x16(C[mt], al0, al1, al2, al3, bh[kk][0], bh[kk][1]);
            }
        }
    }

    #pragma unroll
    for (int mt = 0; mt < 5; mt++) {
        const float blo = b_s[16 * mt + g];
        const float bhi = b_s[16 * mt + g + 8];
        C[mt][0] += blo; C[mt][1] += blo;
        C[mt][2] += bhi; C[mt][3] += bhi;
    }

    __nv_bfloat16* vb = g_v + (size_t)b * CCH * NSP;
    const int nv = n0 + wrp * 8 + 2 * tg;
    #pragma unroll
    for (int mt = 1; mt < 5; mt++) {
        const int ch = 16 * mt + g - 16;
        *(uint32_t*)(vb + (size_t)ch * NSP + nv)       = cvt_bf16x2(C[mt][1], C[mt][0]);
        *(uint32_t*)(vb + (size_t)(ch + 8) * NSP + nv) = cvt_bf16x2(C[mt][3], C[mt][2]);
    }

    {
        const int nl = wrp * 8 + 2 * tg;
        *(float2*)(qk_s + g * QK_STR + nl)       = make_float2(C[0][0], C[0][1]);
        *(float2*)(qk_s + (g + 8) * QK_STR + nl) = make_float2(C[0][2], C[0][3]);
    }
    __syncthreads();

    if (tid < 64) {
        const int nl = tid;
        float* qp = g_q + ((size_t)b * NSP + n0 + nl) * 8;
        float4 q0, q1;
        q0.x = qk_s[0 * QK_STR + nl] * LOG2E;
        q0.y = qk_s[1 * QK_STR + nl] * LOG2E;
        q0.z = qk_s[2 * QK_STR + nl] * LOG2E;
        q0.w = qk_s[3 * QK_STR + nl] * LOG2E;
        q1.x = qk_s[4 * QK_STR + nl] * LOG2E;
        q1.y = qk_s[5 * QK_STR + nl] * LOG2E;
        q1.z = qk_s[6 * QK_STR + nl] * LOG2E;
        q1.w = qk_s[7 * QK_STR + nl] * LOG2E;
        ((float4*)qp)[0] = q0;
        ((float4*)qp)[1] = q1;
    } else if (tid < 128) {
        const int nl = tid - 64;
        uint16_t kh[8], kl[8];
        #pragma unroll
        for (int i = 0; i < 8; i++)
            split_bf16(qk_s[(8 + i) * QK_STR + nl], kh[i], kl[i]);
        uint32_t row[8];
        #pragma unroll
        for (int i = 0; i < 4; i++) {
            row[i]     = (uint32_t)kh[2*i] | ((uint32_t)kh[2*i+1] << 16);
            row[4 + i] = (uint32_t)kl[2*i] | ((uint32_t)kl[2*i+1] << 16);
        }
        uint4* kp = (uint4*)(g_kp + ((size_t)b * NSP + n0 + nl) * 8);
        kp[0] = ((uint4*)row)[0];
        kp[1] = ((uint4*)row)[1];
    }
}

// ---------------------------------------------------------------------------
// Split-KV flash attention, NSPLIT=4 for occupancy (3 CTAs/SM, 24 warps/SM).
// Grid (32, 4, 4) = 512 CTAs x 256 thr. Fused finisher: last-arriving CTA of
// each (b,qt) sums ALL four partials from global in fixed sp order
// (deterministic regardless of arrival order), normalizes, writes residual.
// ---------------------------------------------------------------------------
#define K_STR 48
#define V_STR 272
#define KBUF_SZ (128 * K_STR)
#define VBUF_SZ (64 * V_STR)
#define VBASE   (2 * KBUF_SZ)
#define SMEM_SZ (VBASE + 2 * VBUF_SZ)
#define STAGE_STR 132

__global__ __launch_bounds__(256, 3) void attn_kernel(
    const float* __restrict__ x,
    const float* __restrict__ gamma,
    float* __restrict__ out)
{
    __shared__ __align__(16) char s_buf[SMEM_SZ];
    __shared__ float sinv_s[128];
    __shared__ int s_old;

    const int tid  = threadIdx.x;
    const int wid  = tid >> 5;
    const int lane = tid & 31;
    const int g    = lane >> 2;
    const int tg   = lane & 3;
    const int b    = blockIdx.y;
    const int sp   = blockIdx.z;
    const int qt   = blockIdx.x;
    const int qbase = qt * 128;

    const uint32_t sbase = smem_u32(s_buf);

    const int mat      = lane >> 3;
    const int row_lane = lane & 7;
    const uint32_t k_lm_off = (uint32_t)(((mat >> 1) * 8 + row_lane) * K_STR + (mat & 1) * 16);
    const uint32_t v_lm_off = (uint32_t)(((mat >> 1) * 8 + row_lane) * V_STR + (mat & 1) * 16);

    uint32_t qh_r0, qh_r1, ql_r0, ql_r1;
    {
        const int r0 = qbase + wid * 16 + g;
        float2 q0 = *(const float2*)(g_q + ((size_t)b * NSP + r0) * 8 + tg * 2);
        float2 q1 = *(const float2*)(g_q + ((size_t)b * NSP + r0 + 8) * 8 + tg * 2);
        uint16_t h0, l0, h1, l1;
        split_bf16(q0.x, h0, l0); split_bf16(q0.y, h1, l1);
        qh_r0 = (uint32_t)h0 | ((uint32_t)h1 << 16);
        ql_r0 = (uint32_t)l0 | ((uint32_t)l1 << 16);
        split_bf16(q1.x, h0, l0); split_bf16(q1.y, h1, l1);
        qh_r1 = (uint32_t)h0 | ((uint32_t)h1 << 16);
        ql_r1 = (uint32_t)l0 | ((uint32_t)l1 << 16);
    }

    float oc[8][4];
    #pragma unroll
    for (int t = 0; t < 8; t++)
        #pragma unroll
        for (int i = 0; i < 4; i++) oc[t][i] = 0.f;
    float lsum0 = 0.f, lsum1 = 0.f;

    const uint32_t* gk = g_kp + (size_t)b * NSP * 8;
    const __nv_bfloat16* gv = g_v + (size_t)b * CCH * NSP;

    const int k_key  = tid >> 1;
    const int k_part = tid & 1;
    auto load_tile = [&](int kt, int buf) {
        cp_async16(sbase + buf * KBUF_SZ + k_key * K_STR + k_part * 16,
                   gk + ((size_t)kt * KT + k_key) * 8 + k_part * 4);
        #pragma unroll
        for (int i = 0; i < 4; i++) {
            int idx = tid + i * 256;
            int c = idx >> 4, seg = idx & 15;
            cp_async16(sbase + VBASE + buf * VBUF_SZ + c * V_STR + seg * 16,
                       gv + (size_t)c * NSP + kt * KT + seg * 8);
        }
    };

    const int kt0 = sp * TILES_PER_SPLIT;
    load_tile(kt0, 0);
    CP_COMMIT();

    for (int it = 0; it < TILES_PER_SPLIT; it++) {
        const int cur = it & 1;
        CP_WAIT0();
        __syncthreads();
        if (it + 1 < TILES_PER_SPLIT) {
            load_tile(kt0 + it + 1, cur ^ 1);
            CP_COMMIT();
        }

        const uint32_t k_lm = sbase + cur * KBUF_SZ + k_lm_off;
        const uint32_t v_lm = sbase + VBASE + cur * VBUF_SZ + v_lm_off;

        float    sc[2][4][4];
        uint32_t pa[2][2][4];

        auto S = [&](int c, float scc[4][4]) {
            #pragma unroll
            for (int i = 0; i < 2; i++) {
                const int tp = 2 * c + i;
                uint32_t b00, b01, b10, b11;
                ldsm_x4(b00, b01, b10, b11, k_lm + (uint32_t)(tp * 16 * K_STR));
                #pragma unroll
                for (int j = 0; j < 4; j++) { scc[2*i][j] = 0.f; scc[2*i+1][j] = 0.f; }
                mma_16x8x16(scc[2*i],   qh_r0, qh_r1, qh_r0, qh_r1, b00, b01);
                mma_16x8x8 (scc[2*i],   ql_r0, ql_r1, b00);
                mma_16x8x16(scc[2*i+1], qh_r0, qh_r1, qh_r0, qh_r1, b10, b11);
                mma_16x8x8 (scc[2*i+1], ql_r0, ql_r1, b10);
            }
        };
        auto E = [&](float scc[4][4], uint32_t pac[2][4]) {
            #pragma unroll
            for (int i = 0; i < 2; i++) {
                float e00 = ex2f(scc[2*i][0]),   e01 = ex2f(scc[2*i][1]);
                float e02 = ex2f(scc[2*i][2]),   e03 = ex2f(scc[2*i][3]);
                float e10 = ex2f(scc[2*i+1][0]), e11 = ex2f(scc[2*i+1][1]);
                float e12 = ex2f(scc[2*i+1][2]), e13 = ex2f(scc[2*i+1][3]);
                lsum0 += (e00 + e01) + (e10 + e11);
                lsum1 += (e02 + e03) + (e12 + e13);
                pac[i][0] = cvt_bf16x2(e01, e00);
                pac[i][1] = cvt_bf16x2(e03, e02);
                pac[i][2] = cvt_bf16x2(e11, e10);
                pac[i][3] = cvt_bf16x2(e13, e12);
            }
        };
        auto O = [&](int c, uint32_t pac[2][4]) {
            #pragma unroll
            for (int i = 0; i < 2; i++) {
                const int kk = 2 * c + i;
                #pragma unroll
                for (int tp = 0; tp < 4; tp++) {
                    uint32_t b00, b01, b10, b11;
                    ldsm_x4(b00, b01, b10, b11,
                            v_lm + (uint32_t)(tp * 16 * V_STR + kk * 32));
                    mma_16x8x16(oc[2*tp],   pac[i][0], pac[i][1], pac[i][2], pac[i][3], b00, b01);
                    mma_16x8x16(oc[2*tp+1], pac[i][0], pac[i][1], pac[i][2], pac[i][3], b10, b11);
                }
            }
        };

        S(0, sc[0]);
        E(sc[0], pa[0]);
        #pragma unroll
        for (int c = 0; c < 4; c++) {
            const int curp = c & 1, nxt = curp ^ 1;
            if (c < 3) S(c + 1, sc[nxt]);
            O(c, pa[curp]);
            if (c < 3) E(sc[nxt], pa[nxt]);
        }
    }

    // ---- reduce lsum; publish partials to global ----
    lsum0 += __shfl_xor_sync(0xFFFFFFFF, lsum0, 1);
    lsum0 += __shfl_xor_sync(0xFFFFFFFF, lsum0, 2);
    lsum1 += __shfl_xor_sync(0xFFFFFFFF, lsum1, 1);
    lsum1 += __shfl_xor_sync(0xFFFFFFFF, lsum1, 2);
    const int pbase = ((sp * BATCH + b) * NQT + qt);
    if (tg == 0) {
        g_pl[pbase * 128 + wid * 16 + g]     = lsum0;
        g_pl[pbase * 128 + wid * 16 + g + 8] = lsum1;
    }

    __syncthreads();                       // tile reads done; reuse s_buf
    float* stage = (float*)s_buf;          // [64][STAGE_STR] unnormalized O
    const int n0 = wid * 16 + g;
    #pragma unroll
    for (int t = 0; t < 8; t++) {
        const int c = t * 8 + tg * 2;
        stage[c * STAGE_STR + n0]           = oc[t][0];
        stage[(c + 1) * STAGE_STR + n0]     = oc[t][1];
        stage[c * STAGE_STR + n0 + 8]       = oc[t][2];
        stage[(c + 1) * STAGE_STR + n0 + 8] = oc[t][3];
    }
    __syncthreads();

    float* po = g_po + (size_t)pbase * (CCH * 128);
    for (int idx = tid; idx < CCH * 128; idx += 256) {
        const int c  = idx >> 7;
        const int nn = idx & 127;
        po[idx] = stage[c * STAGE_STR + nn];
    }

    // ---- finisher election (threadfence + atomic, self-resetting) ----
    __threadfence();
    __syncthreads();
    if (tid == 0) s_old = atomicAdd(&g_sem[b * NQT + qt], 1);
    __syncthreads();
    if (s_old != NSPLIT - 1) return;       // non-last CTAs done
    if (tid == 0) g_sem[b * NQT + qt] = 0; // reset for graph replay

    // ---- combine all NSPLIT partials in FIXED sp order (deterministic) ----
    int p[NSPLIT];
    #pragma unroll
    for (int s = 0; s < NSPLIT; s++) p[s] = ((s * BATCH + b) * NQT + qt);

    if (tid < 128) {
        float l = 0.f;
        #pragma unroll
        for (int s = 0; s < NSPLIT; s++) l += g_pl[p[s] * 128 + tid];
        sinv_s[tid] = __ldg(gamma) / l;
    }
    __syncthreads();

    const size_t base = (size_t)b * CCH * NSP + (size_t)qt * 128;
    for (int idx = tid; idx < CCH * 128; idx += 256) {
        const int c  = idx >> 7;
        const int nn = idx & 127;
        float acc = 0.f;
        #pragma unroll
        for (int s = 0; s < NSPLIT; s++)
            acc += g_po[(size_t)p[s] * (CCH * 128) + idx];
        const size_t off = base + (size_t)c * NSP + nn;
        out[off] = x[off] + acc * sinv_s[nn];
    }
}

extern "C" void kernel_launch(void* const* d_in, const int* in_sizes, int n_in,
                              void* d_out, int out_size)
{
    const float* x     = (const float*)d_in[0];
    const float* wq    = (const float*)d_in[1];
    const float* bq    = (const float*)d_in[2];
    const float* wk    = (const float*)d_in[3];
    const float* bk    = (const float*)d_in[4];
    const float* wv    = (const float*)d_in[5];
    const float* bv    = (const float*)d_in[6];
    const float* gamma = (const float*)d_in[7];
    float* out = (float*)d_out;

    dim3 pg(NSP / 64, BATCH);
    proj_kernel<<<pg, 256>>>(x, wq, bq, wk, bk, wv, bv);

    dim3 ag(NQT, BATCH, NSPLIT);
    attn_kernel<<<ag, 256>>>(x, gamma, out);
}